// round 10
// baseline (speedup 1.0000x reference)
#include <cuda_runtime.h>
#include <math.h>

#define NB 64
#define NT 128
#define NN 64     // nodes
#define NC 128    // channels
#define NH 64     // hidden
#define NE 192    // 3 gates * 64
#define TP 68     // padded pitch for transposed 64-wide tiles
#define PM 34     // pitch for half-width (32) adjacency tiles

// Precomputed input-path gate contributions U[b,t,n,e] (biases included). 384 MiB.
static __device__ float g_U[(size_t)NB * NT * NN * NE];
// Pooled hidden means per (b,t), consumed by phase 3 decoder. 2 MiB.
static __device__ float g_pool[(size_t)NB * NT * NH];

__device__ __forceinline__ unsigned smem_u32(const void* p) {
    unsigned r;
    asm("{ .reg .u64 t; cvta.to.shared.u64 t, %1; cvt.u32.u64 %0, t; }" : "=r"(r) : "l"(p));
    return r;
}
__device__ __forceinline__ unsigned cluster_rank() {
    unsigned r; asm("mov.u32 %0, %%cluster_ctarank;" : "=r"(r)); return r;
}
__device__ __forceinline__ void st_peer_f2(unsigned laddr, unsigned peer, float a, float b) {
    unsigned raddr;
    asm volatile("mapa.shared::cluster.u32 %0, %1, %2;" : "=r"(raddr) : "r"(laddr), "r"(peer));
    asm volatile("st.shared::cluster.v2.f32 [%0], {%1, %2};" :: "r"(raddr), "f"(a), "f"(b) : "memory");
}
#define CLUSTER_ARRIVE() asm volatile("barrier.cluster.arrive.aligned;" ::: "memory")
#define CLUSTER_WAIT()   asm volatile("barrier.cluster.wait.aligned;" ::: "memory")
#define CLUSTER_SYNC() do { CLUSTER_ARRIVE(); CLUSTER_WAIT(); } while (0)

__device__ __forceinline__ float rcp_ap(float x) {
    float y; asm("rcp.approx.f32 %0, %1;" : "=f"(y) : "f"(x)); return y;
}
__device__ __forceinline__ float tanh_fast(float x) {
    return 1.0f - 2.0f * rcp_ap(1.0f + __expf(2.0f * x));
}
__device__ __forceinline__ float sig_fast(float x) {
    return rcp_ap(1.0f + __expf(-x));
}

// ---------------------------------------------------------------------------
// Phase 1: per (b,t) tile. grid = 8192, block = 512, 2 CTAs/SM (32 warps).
// Per-thread tile 4n x 2d. Weights/frames from gmem (L2/L1 broadcast).
// smem = 69632 B.
// ---------------------------------------------------------------------------
// outT[d][n] = sum_m PT[d][m] * AT[m][n], 4n x 2d per thread (512 threads)
__device__ __forceinline__ void mmT64_512(float* __restrict__ outT,
                                          const float* __restrict__ PT,
                                          const float* __restrict__ AT,
                                          int n0, int d0)
{
    float acc[2][4];
#pragma unroll
    for (int i = 0; i < 2; i++)
#pragma unroll
        for (int j = 0; j < 4; j++) acc[i][j] = 0.f;

#pragma unroll 4
    for (int m = 0; m < 64; m++) {
        float4 a4 = *(const float4*)&AT[m * TP + n0];
        float av[4] = {a4.x, a4.y, a4.z, a4.w};
        float p0 = PT[d0 * TP + m];
        float p1 = PT[(d0 + 1) * TP + m];
#pragma unroll
        for (int j = 0; j < 4; j++) {
            acc[0][j] += p0 * av[j];
            acc[1][j] += p1 * av[j];
        }
    }
#pragma unroll
    for (int i = 0; i < 2; i++)
        *(float4*)&outT[(d0 + i) * TP + n0] =
            make_float4(acc[i][0], acc[i][1], acc[i][2], acc[i][3]);
}

__global__ void __launch_bounds__(512, 2) phase1_kernel(
    const float* __restrict__ frames, const float* __restrict__ adj,
    const float* __restrict__ encW, const float* __restrict__ encB,
    const float* __restrict__ Wfu, const float* __restrict__ Wgu, const float* __restrict__ Wcu,
    const float* __restrict__ bf, const float* __restrict__ bg, const float* __restrict__ bc)
{
    extern __shared__ float sm[];
    float* sAT = sm;               // 4352
    float* sXT = sm + 4352;        // 4352
    float* sYT = sm + 8704;        // 4352
    float* sZT = sm + 13056;       // 4352

    const int tid = threadIdx.x;
    const int bt = blockIdx.x;
    const float* fr = frames + (size_t)bt * (NC * NN);
    const float* Ap = adj + (size_t)bt * (NN * NN);

    for (int i = tid; i < NN * NN; i += 512)
        sAT[(i & 63) * TP + (i >> 6)] = Ap[i];
    __syncthreads();

    const int n0 = (tid & 15) * 4;   // 4 n per thread (16 slots)
    const int d0 = (tid >> 4) * 2;   // 2 d per thread (32 slots)

    // Encode: xT[d][n] = sum_c encW[c][d] * fr[c][n] + encB[d]
    {
        float acc[2][4];
#pragma unroll
        for (int i = 0; i < 2; i++)
#pragma unroll
            for (int j = 0; j < 4; j++) acc[i][j] = 0.f;
#pragma unroll 4
        for (int c = 0; c < NC; c++) {
            float4 a4 = __ldg((const float4*)&fr[c * 64 + n0]);
            float2 w2 = __ldg((const float2*)&encW[c * 64 + d0]);
            float av[4] = {a4.x, a4.y, a4.z, a4.w};
#pragma unroll
            for (int j = 0; j < 4; j++) {
                acc[0][j] += w2.x * av[j];
                acc[1][j] += w2.y * av[j];
            }
        }
        float2 b2 = __ldg((const float2*)&encB[d0]);
        float bv[2] = {b2.x, b2.y};
#pragma unroll
        for (int i = 0; i < 2; i++)
            *(float4*)&sXT[(d0 + i) * TP + n0] =
                make_float4(acc[i][0] + bv[i], acc[i][1] + bv[i],
                            acc[i][2] + bv[i], acc[i][3] + bv[i]);
    }
    __syncthreads();
    mmT64_512(sYT, sXT, sAT, n0, d0);
    __syncthreads();
    mmT64_512(sZT, sYT, sAT, n0, d0);
    __syncthreads();

    // Gates: U = bias + sum_k y_k @ Wu_k (weights streamed from gmem/L2)
    float accf[2][4], accg[2][4], accc[2][4];
    {
        float2 vf = __ldg((const float2*)&bf[d0]);
        float2 vg = __ldg((const float2*)&bg[d0]);
        float2 vc = __ldg((const float2*)&bc[d0]);
#pragma unroll
        for (int j = 0; j < 4; j++) {
            accf[0][j] = vf.x; accf[1][j] = vf.y;
            accg[0][j] = vg.x; accg[1][j] = vg.y;
            accc[0][j] = vc.x; accc[1][j] = vc.y;
        }
    }
#pragma unroll 1
    for (int k = 0; k < 3; k++) {
        const float* src = (k == 0) ? sXT : ((k == 1) ? sYT : sZT);
        const float* Wf = Wfu + k * 4096;
        const float* Wg = Wgu + k * 4096;
        const float* Wc = Wcu + k * 4096;
#pragma unroll 4
        for (int m = 0; m < 64; m++) {
            float4 x4 = *(const float4*)&src[m * TP + n0];
            float xv[4] = {x4.x, x4.y, x4.z, x4.w};
            float2 wf2 = __ldg((const float2*)&Wf[m * 64 + d0]);
            float2 wg2 = __ldg((const float2*)&Wg[m * 64 + d0]);
            float2 wc2 = __ldg((const float2*)&Wc[m * 64 + d0]);
#pragma unroll
            for (int j = 0; j < 4; j++) {
                accf[0][j] += wf2.x * xv[j];
                accf[1][j] += wf2.y * xv[j];
                accg[0][j] += wg2.x * xv[j];
                accg[1][j] += wg2.y * xv[j];
                accc[0][j] += wc2.x * xv[j];
                accc[1][j] += wc2.y * xv[j];
            }
        }
    }
    float* Ub = g_U + (size_t)bt * (NN * NE);
#pragma unroll
    for (int j = 0; j < 4; j++) {
        int row = (n0 + j) * NE;
        *(float2*)&Ub[row + d0]       = make_float2(accf[0][j], accf[1][j]);
        *(float2*)&Ub[row + 64 + d0]  = make_float2(accg[0][j], accg[1][j]);
        *(float2*)&Ub[row + 128 + d0] = make_float2(accc[0][j], accc[1][j]);
    }
}

// ---------------------------------------------------------------------------
// Phase 2: persistent recurrence, 2-CTA cluster per batch (n-split),
// split arrive/wait + U prefetch + intra-CTA syncs. (unchanged from R9)
// grid = 128 (64 clusters), block = 512.
// ---------------------------------------------------------------------------
__device__ __forceinline__ void gate_hop512(float af[2][2], float ag[2][2], float ac[2][2],
                                            const float* __restrict__ xT,
                                            const float* __restrict__ wb,
                                            int ng0, int e0)
{
#pragma unroll 4
    for (int m = 0; m < 64; m++) {
        float2 x  = *(const float2*)&xT[m * TP + ng0];
        float2 f2 = *(const float2*)&wb[m * NE + e0];
        float2 g2 = *(const float2*)&wb[m * NE + 64 + e0];
        float2 c2 = *(const float2*)&wb[m * NE + 128 + e0];
        af[0][0] += f2.x * x.x;  af[0][1] += f2.x * x.y;
        af[1][0] += f2.y * x.x;  af[1][1] += f2.y * x.y;
        ag[0][0] += g2.x * x.x;  ag[0][1] += g2.x * x.y;
        ag[1][0] += g2.y * x.x;  ag[1][1] += g2.y * x.y;
        ac[0][0] += c2.x * x.x;  ac[0][1] += c2.x * x.y;
        ac[1][0] += c2.y * x.x;  ac[1][1] += c2.y * x.y;
    }
}

__device__ __forceinline__ void mm_half512(float acc[2][2],
                                           const float* __restrict__ PT,
                                           const float* __restrict__ AT,
                                           int d0, int nl0)
{
    acc[0][0] = acc[0][1] = acc[1][0] = acc[1][1] = 0.f;
#pragma unroll 4
    for (int m = 0; m < 64; m++) {
        float2 a2 = *(const float2*)&AT[m * PM + nl0];
        float p0 = PT[d0 * TP + m];
        float p1 = PT[(d0 + 1) * TP + m];
        acc[0][0] += p0 * a2.x;  acc[0][1] += p0 * a2.y;
        acc[1][0] += p1 * a2.x;  acc[1][1] += p1 * a2.y;
    }
}

__global__ void __launch_bounds__(512, 1) __cluster_dims__(2, 1, 1) phase2_kernel(
    const float* __restrict__ adj, const float* __restrict__ h0,
    const float* __restrict__ Wfh, const float* __restrict__ Wgh, const float* __restrict__ Wch,
    float* __restrict__ out)
{
    extern __shared__ float sm[];
    float* sWh  = sm;                 // 36864
    float* sAT  = sm + 36864;         // 2176 (own n-half)
    float* sHT  = sm + 39040;         // 4352 (full width)
    float* sH1T = sm + 43392;         // 4352 (full width, exchanged)
    float* sH2T = sm + 47744;         // 4352 (own half valid only)

    const int tid = threadIdx.x;
    const int b = blockIdx.x >> 1;
    const unsigned rank = cluster_rank();
    const unsigned peer = rank ^ 1u;
    const int halfbase = (int)rank * 32;

    for (int i = tid; i < 3 * 4096; i += 512) {
        int k = i >> 12; int r = i & 4095; int m = r >> 6; int e = r & 63;
        sWh[(k * 64 + m) * NE + e]       = Wfh[i];
        sWh[(k * 64 + m) * NE + 64 + e]  = Wgh[i];
        sWh[(k * 64 + m) * NE + 128 + e] = Wch[i];
    }
    for (int i = tid; i < 4096; i += 512)
        sHT[(i & 63) * TP + (i >> 6)] = h0[b * 4096 + i];
    __syncthreads();
    CLUSTER_SYNC();
    CLUSTER_ARRIVE();   // pre-arm: loop starts with WAIT

    const unsigned u_sHT  = smem_u32(sHT);
    const unsigned u_sH1T = smem_u32(sH1T);

    const int nl0 = (tid & 15) * 2;        // local n (0..30)
    const int ng0 = halfbase + nl0;        // global n
    const int e0  = (tid >> 4) * 2;        // e/d tile base (0..62)

    // U prefetch registers (step 0 preload)
    float2 puf[2], pug[2], puc[2];
    {
        const float* Ub = g_U + ((size_t)(b * NT)) * (NN * NE);
#pragma unroll
        for (int j = 0; j < 2; j++) {
            int row = (ng0 + j) * NE;
            puf[j] = *(const float2*)&Ub[row + e0];
            pug[j] = *(const float2*)&Ub[row + 64 + e0];
            puc[j] = *(const float2*)&Ub[row + 128 + e0];
        }
    }

    for (int t = 0; t < NT; t++) {
        float af[2][2], ag[2][2], ac[2][2];
#pragma unroll
        for (int j = 0; j < 2; j++) {
            af[0][j] = puf[j].x; af[1][j] = puf[j].y;
            ag[0][j] = pug[j].x; ag[1][j] = pug[j].y;
            ac[0][j] = puc[j].x; ac[1][j] = puc[j].y;
        }
        {
            int btn = b * NT + t + 1;
            if (btn > NB * NT - 1) btn = NB * NT - 1;
            const float* Ub = g_U + (size_t)btn * (NN * NE);
#pragma unroll
            for (int j = 0; j < 2; j++) {
                int row = (ng0 + j) * NE;
                puf[j] = *(const float2*)&Ub[row + e0];
                pug[j] = *(const float2*)&Ub[row + 64 + e0];
                puc[j] = *(const float2*)&Ub[row + 128 + e0];
            }
        }
        const float* Ap = adj + ((size_t)(b * NT + t)) * 4096 + (size_t)halfbase * 64;
        for (int i = tid; i < 2048; i += 512) {
            int nl = i >> 6, m = i & 63;
            sAT[m * PM + nl] = Ap[nl * 64 + m];
        }

        // hop 0: gates over x = h (own n columns — local)
        gate_hop512(af, ag, ac, sHT, sWh, ng0, e0);

        CLUSTER_WAIT();    // full h(t) visible (peer h_new push of step t-1)
        __syncthreads();   // intra-CTA: sAT staging complete before mm1

        // pool of h(t-1)
        if (rank == 0 && t > 0) {
            int d = tid >> 3, q = tid & 7;
            float s = 0.f;
            const float* row = &sHT[d * TP + q * 8];
#pragma unroll
            for (int nn = 0; nn < 8; nn++) s += row[nn];
            s += __shfl_xor_sync(0xFFFFFFFFu, s, 1);
            s += __shfl_xor_sync(0xFFFFFFFFu, s, 2);
            s += __shfl_xor_sync(0xFFFFFFFFu, s, 4);
            if (q == 0)
                g_pool[((size_t)(b * NT + t - 1)) * NH + d] = s * (1.0f / 64.0f);
        }

        // mm1: h1 = A h (own rows); write local + push peer; arrive
        float mmv[2][2];
        mm_half512(mmv, sHT, sAT, e0, nl0);
#pragma unroll
        for (int i = 0; i < 2; i++) {
            int off = (e0 + i) * TP + ng0;
            *(float2*)&sH1T[off] = make_float2(mmv[i][0], mmv[i][1]);
            st_peer_f2(u_sH1T + (unsigned)off * 4u, peer, mmv[i][0], mmv[i][1]);
        }
        CLUSTER_ARRIVE();
        __syncthreads();   // local sH1T writes visible before hop1 reads

        // hop 1: gates over x = h1 (own n columns — local)
        gate_hop512(af, ag, ac, sH1T, sWh + 64 * NE, ng0, e0);

        CLUSTER_WAIT();    // full h1 visible

        // mm2: h2 = A h1 (own rows, local only)
        mm_half512(mmv, sH1T, sAT, e0, nl0);
#pragma unroll
        for (int i = 0; i < 2; i++)
            *(float2*)&sH2T[(e0 + i) * TP + ng0] = make_float2(mmv[i][0], mmv[i][1]);
        __syncthreads();   // sH2T complete before hop2

        // hop 2: gates over x = h2 (own half)
        gate_hop512(af, ag, ac, sH2T, sWh + 128 * NE, ng0, e0);

        // Nonlinearity -> h_new own tile; write local + push peer; arrive
#pragma unroll
        for (int i = 0; i < 2; i++) {
            float hv0, hv1;
            {
                float f = sig_fast(af[i][0]);
                float tg = tanh_fast(ag[i][0]);
                float tc = tanh_fast(ac[i][0]);
                hv0 = f * (tg - tc) + tc;
            }
            {
                float f = sig_fast(af[i][1]);
                float tg = tanh_fast(ag[i][1]);
                float tc = tanh_fast(ac[i][1]);
                hv1 = f * (tg - tc) + tc;
            }
            int off = (e0 + i) * TP + ng0;
            *(float2*)&sHT[off] = make_float2(hv0, hv1);
            st_peer_f2(u_sHT + (unsigned)off * 4u, peer, hv0, hv1);
        }
        CLUSTER_ARRIVE();
        __syncthreads();   // own-col h_new + sAT reuse protected for next iter
    }

    CLUSTER_WAIT();   // final h full everywhere

    if (rank == 0) {
        {
            int d = tid >> 3, q = tid & 7;
            float s = 0.f;
            const float* row = &sHT[d * TP + q * 8];
#pragma unroll
            for (int nn = 0; nn < 8; nn++) s += row[nn];
            s += __shfl_xor_sync(0xFFFFFFFFu, s, 1);
            s += __shfl_xor_sync(0xFFFFFFFFu, s, 2);
            s += __shfl_xor_sync(0xFFFFFFFFu, s, 4);
            if (q == 0)
                g_pool[((size_t)(b * NT + NT - 1)) * NH + d] = s * (1.0f / 64.0f);
        }
        float* fh = out + (size_t)NB * NT * 6 + (size_t)b * (NN * NH);
        for (int i = tid; i < 4096; i += 512)
            fh[i] = sHT[(i & 63) * TP + (i >> 6)];
    }
}

// ---------------------------------------------------------------------------
// Phase 3: decoder MLP per (b,t). grid = 8192, block = 128.
// ---------------------------------------------------------------------------
__global__ void __launch_bounds__(128, 8) phase3_kernel(
    const float* __restrict__ dW1, const float* __restrict__ db1,
    const float* __restrict__ dW2, const float* __restrict__ db2,
    const float* __restrict__ dW3, const float* __restrict__ db3,
    const float* __restrict__ osc, const float* __restrict__ obi,
    float* __restrict__ out)
{
    __shared__ float sp[64];
    __shared__ float z1[128];
    __shared__ float z2[64];
    const int bt = blockIdx.x;
    const int tid = threadIdx.x;

    if (tid < 64) sp[tid] = g_pool[(size_t)bt * NH + tid];
    __syncthreads();
    {
        float a = db1[tid];
#pragma unroll 4
        for (int d = 0; d < 64; d++) a += sp[d] * dW1[d * 128 + tid];
        z1[tid] = fmaxf(a, 0.f);
    }
    __syncthreads();
    if (tid < 64) {
        float a = db2[tid];
#pragma unroll 4
        for (int i = 0; i < 128; i++) a += z1[i] * dW2[i * 64 + tid];
        z2[tid] = fmaxf(a, 0.f);
    }
    __syncthreads();
    if (tid < 6) {
        float a = db3[tid];
#pragma unroll 4
        for (int j = 0; j < 64; j++) a += z2[j] * dW3[j * 6 + tid];
        out[(size_t)bt * 6 + tid] = a * osc[tid] + obi[tid];
    }
}

extern "C" void kernel_launch(void* const* d_in, const int* in_sizes, int n_in,
                              void* d_out, int out_size) {
    const float* frames = (const float*)d_in[0];
    const float* adj    = (const float*)d_in[1];
    const float* h0     = (const float*)d_in[2];
    const float* encW   = (const float*)d_in[3];
    const float* encB   = (const float*)d_in[4];
    const float* Wfh    = (const float*)d_in[5];
    const float* Wfu    = (const float*)d_in[6];
    const float* bf     = (const float*)d_in[7];
    const float* Wgh    = (const float*)d_in[8];
    const float* Wgu    = (const float*)d_in[9];
    const float* bg     = (const float*)d_in[10];
    const float* Wch    = (const float*)d_in[11];
    const float* Wcu    = (const float*)d_in[12];
    const float* bc     = (const float*)d_in[13];
    const float* dW1    = (const float*)d_in[14];
    const float* db1    = (const float*)d_in[15];
    const float* dW2    = (const float*)d_in[16];
    const float* db2    = (const float*)d_in[17];
    const float* dW3    = (const float*)d_in[18];
    const float* db3    = (const float*)d_in[19];
    const float* osc    = (const float*)d_in[20];
    const float* obi    = (const float*)d_in[21];
    float* out = (float*)d_out;

    const int smem1 = 17408 * 4;   // 69632 B  -> 2 CTAs/SM (32 warps)
    const int smem2 = 52096 * 4;   // 208384 B
    cudaFuncSetAttribute(phase1_kernel, cudaFuncAttributeMaxDynamicSharedMemorySize, smem1);
    cudaFuncSetAttribute(phase2_kernel, cudaFuncAttributeMaxDynamicSharedMemorySize, smem2);

    phase1_kernel<<<NB * NT, 512, smem1>>>(frames, adj, encW, encB,
                                           Wfu, Wgu, Wcu, bf, bg, bc);
    phase2_kernel<<<NB * 2, 512, smem2>>>(adj, h0, Wfh, Wgh, Wch, out);
    phase3_kernel<<<NB * NT, 128>>>(dW1, db1, dW2, db2, dW3, db3, osc, obi, out);
}

// round 13
// speedup vs baseline: 1.1169x; 1.1169x over previous
#include <cuda_runtime.h>
#include <math.h>

#define NB 64
#define NT 128
#define NN 64
#define NC 128
#define NH 64
#define NE 192
#define TP 68
#define PM 34
#define PY 196   // natural Y pitch (floats): bank-conflict-free A-fragment loads

// U[b,t,n,e] fp32 (biases included). 384 MiB.
static __device__ float g_U[(size_t)NB * NT * NN * NE];
// Pooled hidden means per (b,t). 2 MiB.
static __device__ float g_pool[(size_t)NB * NT * NH];

__device__ __forceinline__ unsigned smem_u32(const void* p) {
    unsigned r;
    asm("{ .reg .u64 t; cvta.to.shared.u64 t, %1; cvt.u32.u64 %0, t; }" : "=r"(r) : "l"(p));
    return r;
}
__device__ __forceinline__ unsigned cluster_rank() {
    unsigned r; asm("mov.u32 %0, %%cluster_ctarank;" : "=r"(r)); return r;
}
__device__ __forceinline__ void st_peer_f2(unsigned laddr, unsigned peer, float a, float b) {
    unsigned raddr;
    asm volatile("mapa.shared::cluster.u32 %0, %1, %2;" : "=r"(raddr) : "r"(laddr), "r"(peer));
    asm volatile("st.shared::cluster.v2.f32 [%0], {%1, %2};" :: "r"(raddr), "f"(a), "f"(b) : "memory");
}
#define CLUSTER_ARRIVE() asm volatile("barrier.cluster.arrive.aligned;" ::: "memory")
#define CLUSTER_WAIT()   asm volatile("barrier.cluster.wait.aligned;" ::: "memory")
#define CLUSTER_SYNC() do { CLUSTER_ARRIVE(); CLUSTER_WAIT(); } while (0)

__device__ __forceinline__ float rcp_ap(float x) {
    float y; asm("rcp.approx.f32 %0, %1;" : "=f"(y) : "f"(x)); return y;
}
__device__ __forceinline__ float tanh_fast(float x) {
    return 1.0f - 2.0f * rcp_ap(1.0f + __expf(2.0f * x));
}
__device__ __forceinline__ float sig_fast(float x) {
    return rcp_ap(1.0f + __expf(-x));
}
__device__ __forceinline__ unsigned f2tf(float x) {
    unsigned u; asm("cvt.rna.tf32.f32 %0, %1;" : "=r"(u) : "f"(x)); return u;
}
__device__ __forceinline__ void mma_tf32(float c[4], const unsigned a[4],
                                         unsigned b0, unsigned b1) {
    asm volatile(
        "mma.sync.aligned.m16n8k8.row.col.f32.tf32.tf32.f32 "
        "{%0,%1,%2,%3}, {%4,%5,%6,%7}, {%8,%9}, {%0,%1,%2,%3};"
        : "+f"(c[0]), "+f"(c[1]), "+f"(c[2]), "+f"(c[3])
        : "r"(a[0]), "r"(a[1]), "r"(a[2]), "r"(a[3]), "r"(b0), "r"(b1));
}

// ---------------------------------------------------------------------------
// Phase 1 (fused): scalar encode + A-hops, then tf32 mma.sync gate-GEMM.
// grid = 8192, block = 256, 2 CTAs/SM. smem = 102400 B.
// ---------------------------------------------------------------------------
__global__ void __launch_bounds__(256, 2) phase1_kernel(
    const float* __restrict__ frames, const float* __restrict__ adj,
    const float* __restrict__ encW, const float* __restrict__ encB,
    const float* __restrict__ Wfu, const float* __restrict__ Wgu, const float* __restrict__ Wcu,
    const float* __restrict__ bf, const float* __restrict__ bg, const float* __restrict__ bc)
{
    extern __shared__ float sm[];
    float* sAT = sm;               // 4352
    float* sXT = sm + 4352;        // 4352
    float* sYT = sm + 8704;        // 4352
    float* sY  = sm + 13056;       // 64 x PY natural [n][kcat]: 12544

    const int tid = threadIdx.x;
    const int bt = blockIdx.x;
    const float* fr = frames + (size_t)bt * (NC * NN);
    const float* Ap = adj + (size_t)bt * (NN * NN);

    for (int i = tid; i < NN * NN; i += 256)
        sAT[(i & 63) * TP + (i >> 6)] = Ap[i];
    __syncthreads();

    const int n0 = (tid & 15) * 4;
    const int d0 = (tid >> 4) * 4;

    float acc[4][4];
    // Encode: x[n][d] = sum_c encW[c][d] * fr[c][n] + encB[d]
    {
#pragma unroll
        for (int i = 0; i < 4; i++)
#pragma unroll
            for (int j = 0; j < 4; j++) acc[i][j] = 0.f;
#pragma unroll 4
        for (int c = 0; c < NC; c++) {
            float4 a4 = __ldg((const float4*)&fr[c * 64 + n0]);
            float4 w4 = __ldg((const float4*)&encW[c * 64 + d0]);
            float av[4] = {a4.x, a4.y, a4.z, a4.w};
            float wv[4] = {w4.x, w4.y, w4.z, w4.w};
#pragma unroll
            for (int i = 0; i < 4; i++)
#pragma unroll
                for (int j = 0; j < 4; j++) acc[i][j] += wv[i] * av[j];
        }
        float4 b4 = __ldg((const float4*)&encB[d0]);
        float bv[4] = {b4.x, b4.y, b4.z, b4.w};
#pragma unroll
        for (int i = 0; i < 4; i++)
#pragma unroll
            for (int j = 0; j < 4; j++) acc[i][j] += bv[i];
#pragma unroll
        for (int i = 0; i < 4; i++)
            *(float4*)&sXT[(d0 + i) * TP + n0] =
                make_float4(acc[i][0], acc[i][1], acc[i][2], acc[i][3]);
#pragma unroll
        for (int j = 0; j < 4; j++)
            *(float4*)&sY[(n0 + j) * PY + d0] =
                make_float4(acc[0][j], acc[1][j], acc[2][j], acc[3][j]);
    }
    __syncthreads();

    // y1 = A x
    {
#pragma unroll
        for (int i = 0; i < 4; i++)
#pragma unroll
            for (int j = 0; j < 4; j++) acc[i][j] = 0.f;
#pragma unroll 4
        for (int m = 0; m < 64; m++) {
            float4 a4 = *(const float4*)&sAT[m * TP + n0];
            float av[4] = {a4.x, a4.y, a4.z, a4.w};
            float p[4];
#pragma unroll
            for (int i = 0; i < 4; i++) p[i] = sXT[(d0 + i) * TP + m];
#pragma unroll
            for (int i = 0; i < 4; i++)
#pragma unroll
                for (int j = 0; j < 4; j++) acc[i][j] += p[i] * av[j];
        }
#pragma unroll
        for (int i = 0; i < 4; i++)
            *(float4*)&sYT[(d0 + i) * TP + n0] =
                make_float4(acc[i][0], acc[i][1], acc[i][2], acc[i][3]);
#pragma unroll
        for (int j = 0; j < 4; j++)
            *(float4*)&sY[(n0 + j) * PY + 64 + d0] =
                make_float4(acc[0][j], acc[1][j], acc[2][j], acc[3][j]);
    }
    __syncthreads();

    // y2 = A y1
    {
#pragma unroll
        for (int i = 0; i < 4; i++)
#pragma unroll
            for (int j = 0; j < 4; j++) acc[i][j] = 0.f;
#pragma unroll 4
        for (int m = 0; m < 64; m++) {
            float4 a4 = *(const float4*)&sAT[m * TP + n0];
            float av[4] = {a4.x, a4.y, a4.z, a4.w};
            float p[4];
#pragma unroll
            for (int i = 0; i < 4; i++) p[i] = sYT[(d0 + i) * TP + m];
#pragma unroll
            for (int i = 0; i < 4; i++)
#pragma unroll
                for (int j = 0; j < 4; j++) acc[i][j] += p[i] * av[j];
        }
#pragma unroll
        for (int j = 0; j < 4; j++)
            *(float4*)&sY[(n0 + j) * PY + 128 + d0] =
                make_float4(acc[0][j], acc[1][j], acc[2][j], acc[3][j]);
    }
    __syncthreads();

    // ---------- tf32 mma.sync gate-GEMM: U[64,192] = sY[64,192] @ Wcat[192,192] + bias
    const int w = tid >> 5;
    const int lane = tid & 31;
    const int g = lane >> 2;        // 0..7
    const int t4 = lane & 3;        // 0..3
    const int e0 = w * 24;          // warp e-slice

    // per-n-tile gate base pointers / in-gate column
    const float* Wp[3];
    const float* Bp[3];
    int dcn[3];
#pragma unroll
    for (int nt = 0; nt < 3; nt++) {
        int e = e0 + nt * 8;
        int gate = e >> 6;
        dcn[nt] = e & 63;
        Wp[nt] = (gate == 0) ? Wfu : ((gate == 1) ? Wgu : Wcu);
        Bp[nt] = (gate == 0) ? bf  : ((gate == 1) ? bg  : bc);
    }

    // accumulators [mt][nt][4], init to bias
    float cacc[4][3][4];
#pragma unroll
    for (int nt = 0; nt < 3; nt++) {
        float b0v = __ldg(Bp[nt] + dcn[nt] + 2 * t4);
        float b1v = __ldg(Bp[nt] + dcn[nt] + 2 * t4 + 1);
#pragma unroll
        for (int mt = 0; mt < 4; mt++) {
            cacc[mt][nt][0] = b0v; cacc[mt][nt][1] = b1v;
            cacc[mt][nt][2] = b0v; cacc[mt][nt][3] = b1v;
        }
    }

#pragma unroll 1
    for (int kt = 0; kt < 24; kt++) {
        const int hop = kt >> 3;
        const int dk0 = (kt & 7) * 8;
        const int kc = kt * 8;

        // A: f32 loads + hi conversion (a0=(g,t4) a1=(g+8,t4) a2=(g,t4+4) a3=(g+8,t4+4))
        float afv[4][4];
        unsigned ah[4][4];
#pragma unroll
        for (int mt = 0; mt < 4; mt++) {
            int r0 = (mt * 16 + g) * PY;
            int r1 = r0 + 8 * PY;
            afv[mt][0] = sY[r0 + kc + t4];
            afv[mt][1] = sY[r1 + kc + t4];
            afv[mt][2] = sY[r0 + kc + t4 + 4];
            afv[mt][3] = sY[r1 + kc + t4 + 4];
#pragma unroll
            for (int q = 0; q < 4; q++) ah[mt][q] = f2tf(afv[mt][q]);
        }

        // B per n-tile: hi (kept) + lo (transient); terms Ah*Bh and Ah*Bl
        unsigned bh[3][2];
#pragma unroll
        for (int nt = 0; nt < 3; nt++) {
            const float* W = Wp[nt];
            int base = hop * 4096 + (dk0 + t4) * 64 + dcn[nt] + g;
            float w0 = __ldg(W + base);
            float w1 = __ldg(W + base + 256);   // +4 rows of k
            bh[nt][0] = f2tf(w0);
            bh[nt][1] = f2tf(w1);
            unsigned bl0 = f2tf(w0 - __uint_as_float(bh[nt][0]));
            unsigned bl1 = f2tf(w1 - __uint_as_float(bh[nt][1]));
#pragma unroll
            for (int mt = 0; mt < 4; mt++) {
                mma_tf32(cacc[mt][nt], ah[mt], bh[nt][0], bh[nt][1]);
                mma_tf32(cacc[mt][nt], ah[mt], bl0, bl1);
            }
        }

        // Al pass: term Al*Bh
        unsigned al[4][4];
#pragma unroll
        for (int mt = 0; mt < 4; mt++)
#pragma unroll
            for (int q = 0; q < 4; q++)
                al[mt][q] = f2tf(afv[mt][q] - __uint_as_float(ah[mt][q]));
#pragma unroll
        for (int nt = 0; nt < 3; nt++)
#pragma unroll
            for (int mt = 0; mt < 4; mt++)
                mma_tf32(cacc[mt][nt], al[mt], bh[nt][0], bh[nt][1]);
    }

    // store U
    float* Ub = g_U + (size_t)bt * (NN * NE);
#pragma unroll
    for (int mt = 0; mt < 4; mt++) {
        int row = mt * 16 + g;
#pragma unroll
        for (int nt = 0; nt < 3; nt++) {
            int col = e0 + nt * 8 + 2 * t4;
            *(float2*)&Ub[row * NE + col] = make_float2(cacc[mt][nt][0], cacc[mt][nt][1]);
            *(float2*)&Ub[(row + 8) * NE + col] = make_float2(cacc[mt][nt][2], cacc[mt][nt][3]);
        }
    }
}

// ---------------------------------------------------------------------------
// Phase 2: persistent recurrence (R9, passing). grid 128 clusters-of-2, block 512.
// ---------------------------------------------------------------------------
__device__ __forceinline__ void gate_hop512(float af[2][2], float ag[2][2], float ac[2][2],
                                            const float* __restrict__ xT,
                                            const float* __restrict__ wb,
                                            int ng0, int e0)
{
#pragma unroll 4
    for (int m = 0; m < 64; m++) {
        float2 x  = *(const float2*)&xT[m * TP + ng0];
        float2 f2 = *(const float2*)&wb[m * NE + e0];
        float2 g2 = *(const float2*)&wb[m * NE + 64 + e0];
        float2 c2 = *(const float2*)&wb[m * NE + 128 + e0];
        af[0][0] += f2.x * x.x;  af[0][1] += f2.x * x.y;
        af[1][0] += f2.y * x.x;  af[1][1] += f2.y * x.y;
        ag[0][0] += g2.x * x.x;  ag[0][1] += g2.x * x.y;
        ag[1][0] += g2.y * x.x;  ag[1][1] += g2.y * x.y;
        ac[0][0] += c2.x * x.x;  ac[0][1] += c2.x * x.y;
        ac[1][0] += c2.y * x.x;  ac[1][1] += c2.y * x.y;
    }
}

__device__ __forceinline__ void mm_half512(float acc[2][2],
                                           const float* __restrict__ PT,
                                           const float* __restrict__ AT,
                                           int d0, int nl0)
{
    acc[0][0] = acc[0][1] = acc[1][0] = acc[1][1] = 0.f;
#pragma unroll 4
    for (int m = 0; m < 64; m++) {
        float2 a2 = *(const float2*)&AT[m * PM + nl0];
        float p0 = PT[d0 * TP + m];
        float p1 = PT[(d0 + 1) * TP + m];
        acc[0][0] += p0 * a2.x;  acc[0][1] += p0 * a2.y;
        acc[1][0] += p1 * a2.x;  acc[1][1] += p1 * a2.y;
    }
}

__global__ void __launch_bounds__(512, 1) __cluster_dims__(2, 1, 1) phase2_kernel(
    const float* __restrict__ adj, const float* __restrict__ h0,
    const float* __restrict__ Wfh, const float* __restrict__ Wgh, const float* __restrict__ Wch,
    float* __restrict__ out)
{
    extern __shared__ float sm[];
    float* sWh  = sm;                 // 36864
    float* sAT  = sm + 36864;         // 2176
    float* sHT  = sm + 39040;         // 4352
    float* sH1T = sm + 43392;         // 4352
    float* sH2T = sm + 47744;         // 4352

    const int tid = threadIdx.x;
    const int b = blockIdx.x >> 1;
    const unsigned rank = cluster_rank();
    const unsigned peer = rank ^ 1u;
    const int halfbase = (int)rank * 32;

    for (int i = tid; i < 3 * 4096; i += 512) {
        int k = i >> 12; int r = i & 4095; int m = r >> 6; int e = r & 63;
        sWh[(k * 64 + m) * NE + e]       = Wfh[i];
        sWh[(k * 64 + m) * NE + 64 + e]  = Wgh[i];
        sWh[(k * 64 + m) * NE + 128 + e] = Wch[i];
    }
    for (int i = tid; i < 4096; i += 512)
        sHT[(i & 63) * TP + (i >> 6)] = h0[b * 4096 + i];
    __syncthreads();
    CLUSTER_SYNC();
    CLUSTER_ARRIVE();

    const unsigned u_sHT  = smem_u32(sHT);
    const unsigned u_sH1T = smem_u32(sH1T);

    const int nl0 = (tid & 15) * 2;
    const int ng0 = halfbase + nl0;
    const int e0  = (tid >> 4) * 2;

    float2 puf[2], pug[2], puc[2];
    {
        const float* Ub = g_U + ((size_t)(b * NT)) * (NN * NE);
#pragma unroll
        for (int j = 0; j < 2; j++) {
            int row = (ng0 + j) * NE;
            puf[j] = *(const float2*)&Ub[row + e0];
            pug[j] = *(const float2*)&Ub[row + 64 + e0];
            puc[j] = *(const float2*)&Ub[row + 128 + e0];
        }
    }

    for (int t = 0; t < NT; t++) {
        float af[2][2], ag[2][2], ac[2][2];
#pragma unroll
        for (int j = 0; j < 2; j++) {
            af[0][j] = puf[j].x; af[1][j] = puf[j].y;
            ag[0][j] = pug[j].x; ag[1][j] = pug[j].y;
            ac[0][j] = puc[j].x; ac[1][j] = puc[j].y;
        }
        {
            int btn = b * NT + t + 1;
            if (btn > NB * NT - 1) btn = NB * NT - 1;
            const float* Ub = g_U + (size_t)btn * (NN * NE);
#pragma unroll
            for (int j = 0; j < 2; j++) {
                int row = (ng0 + j) * NE;
                puf[j] = *(const float2*)&Ub[row + e0];
                pug[j] = *(const float2*)&Ub[row + 64 + e0];
                puc[j] = *(const float2*)&Ub[row + 128 + e0];
            }
        }
        const float* Ap = adj + ((size_t)(b * NT + t)) * 4096 + (size_t)halfbase * 64;
        for (int i = tid; i < 2048; i += 512) {
            int nl = i >> 6, m = i & 63;
            sAT[m * PM + nl] = Ap[nl * 64 + m];
        }

        gate_hop512(af, ag, ac, sHT, sWh, ng0, e0);

        CLUSTER_WAIT();
        __syncthreads();

        if (rank == 0 && t > 0) {
            int d = tid >> 3, q = tid & 7;
            float s = 0.f;
            const float* row = &sHT[d * TP + q * 8];
#pragma unroll
            for (int nn = 0; nn < 8; nn++) s += row[nn];
            s += __shfl_xor_sync(0xFFFFFFFFu, s, 1);
            s += __shfl_xor_sync(0xFFFFFFFFu, s, 2);
            s += __shfl_xor_sync(0xFFFFFFFFu, s, 4);
            if (q == 0)
                g_pool[((size_t)(b * NT + t - 1)) * NH + d] = s * (1.0f / 64.0f);
        }

        float mmv[2][2];
        mm_half512(mmv, sHT, sAT, e0, nl0);
#pragma unroll
        for (int i = 0; i < 2; i++) {
            int off = (e0 + i) * TP + ng0;
            *(float2*)&sH1T[off] = make_float2(mmv[i][0], mmv[i][1]);
            st_peer_f2(u_sH1T + (unsigned)off * 4u, peer, mmv[i][0], mmv[i][1]);
        }
        CLUSTER_ARRIVE();
        __syncthreads();

        gate_hop512(af, ag, ac, sH1T, sWh + 64 * NE, ng0, e0);

        CLUSTER_WAIT();

        mm_half512(mmv, sH1T, sAT, e0, nl0);
#pragma unroll
        for (int i = 0; i < 2; i++)
            *(float2*)&sH2T[(e0 + i) * TP + ng0] = make_float2(mmv[i][0], mmv[i][1]);
        __syncthreads();

        gate_hop512(af, ag, ac, sH2T, sWh + 128 * NE, ng0, e0);

#pragma unroll
        for (int i = 0; i < 2; i++) {
            float hv0, hv1;
            {
                float f = sig_fast(af[i][0]);
                float tg = tanh_fast(ag[i][0]);
                float tc = tanh_fast(ac[i][0]);
                hv0 = f * (tg - tc) + tc;
            }
            {
                float f = sig_fast(af[i][1]);
                float tg = tanh_fast(ag[i][1]);
                float tc = tanh_fast(ac[i][1]);
                hv1 = f * (tg - tc) + tc;
            }
            int off = (e0 + i) * TP + ng0;
            *(float2*)&sHT[off] = make_float2(hv0, hv1);
            st_peer_f2(u_sHT + (unsigned)off * 4u, peer, hv0, hv1);
        }
        CLUSTER_ARRIVE();
        __syncthreads();
    }

    CLUSTER_WAIT();

    if (rank == 0) {
        {
            int d = tid >> 3, q = tid & 7;
            float s = 0.f;
            const float* row = &sHT[d * TP + q * 8];
#pragma unroll
            for (int nn = 0; nn < 8; nn++) s += row[nn];
            s += __shfl_xor_sync(0xFFFFFFFFu, s, 1);
            s += __shfl_xor_sync(0xFFFFFFFFu, s, 2);
            s += __shfl_xor_sync(0xFFFFFFFFu, s, 4);
            if (q == 0)
                g_pool[((size_t)(b * NT + NT - 1)) * NH + d] = s * (1.0f / 64.0f);
        }
        float* fh = out + (size_t)NB * NT * 6 + (size_t)b * (NN * NH);
        for (int i = tid; i < 4096; i += 512)
            fh[i] = sHT[(i & 63) * TP + (i >> 6)];
    }
}

// ---------------------------------------------------------------------------
// Phase 3: decoder MLP per (b,t). grid 8192, block 128.
// ---------------------------------------------------------------------------
__global__ void __launch_bounds__(128, 8) phase3_kernel(
    const float* __restrict__ dW1, const float* __restrict__ db1,
    const float* __restrict__ dW2, const float* __restrict__ db2,
    const float* __restrict__ dW3, const float* __restrict__ db3,
    const float* __restrict__ osc, const float* __restrict__ obi,
    float* __restrict__ out)
{
    __shared__ float sp[64];
    __shared__ float z1[128];
    __shared__ float z2[64];
    const int bt = blockIdx.x;
    const int tid = threadIdx.x;

    if (tid < 64) sp[tid] = g_pool[(size_t)bt * NH + tid];
    __syncthreads();
    {
        float a = db1[tid];
#pragma unroll 4
        for (int d = 0; d < 64; d++) a += sp[d] * dW1[d * 128 + tid];
        z1[tid] = fmaxf(a, 0.f);
    }
    __syncthreads();
    if (tid < 64) {
        float a = db2[tid];
#pragma unroll 4
        for (int i = 0; i < 128; i++) a += z1[i] * dW2[i * 64 + tid];
        z2[tid] = fmaxf(a, 0.f);
    }
    __syncthreads();
    if (tid < 6) {
        float a = db3[tid];
#pragma unroll 4
        for (int j = 0; j < 64; j++) a += z2[j] * dW3[j * 6 + tid];
        out[(size_t)bt * 6 + tid] = a * osc[tid] + obi[tid];
    }
}

extern "C" void kernel_launch(void* const* d_in, const int* in_sizes, int n_in,
                              void* d_out, int out_size) {
    const float* frames = (const float*)d_in[0];
    const float* adj    = (const float*)d_in[1];
    const float* h0     = (const float*)d_in[2];
    const float* encW   = (const float*)d_in[3];
    const float* encB   = (const float*)d_in[4];
    const float* Wfh    = (const float*)d_in[5];
    const float* Wfu    = (const float*)d_in[6];
    const float* bf     = (const float*)d_in[7];
    const float* Wgh    = (const float*)d_in[8];
    const float* Wgu    = (const float*)d_in[9];
    const float* bg     = (const float*)d_in[10];
    const float* Wch    = (const float*)d_in[11];
    const float* Wcu    = (const float*)d_in[12];
    const float* bc     = (const float*)d_in[13];
    const float* dW1    = (const float*)d_in[14];
    const float* db1    = (const float*)d_in[15];
    const float* dW2    = (const float*)d_in[16];
    const float* db2    = (const float*)d_in[17];
    const float* dW3    = (const float*)d_in[18];
    const float* db3    = (const float*)d_in[19];
    const float* osc    = (const float*)d_in[20];
    const float* obi    = (const float*)d_in[21];
    float* out = (float*)d_out;

    const int smem1 = 25600 * 4;   // 102400 B -> 2 CTAs/SM
    const int smem2 = 52096 * 4;   // 208384 B
    cudaFuncSetAttribute(phase1_kernel, cudaFuncAttributeMaxDynamicSharedMemorySize, smem1);
    cudaFuncSetAttribute(phase2_kernel, cudaFuncAttributeMaxDynamicSharedMemorySize, smem2);

    phase1_kernel<<<NB * NT, 256, smem1>>>(frames, adj, encW, encB,
                                           Wfu, Wgu, Wcu, bf, bg, bc);
    phase2_kernel<<<NB * 2, 512, smem2>>>(adj, h0, Wfh, Wgh, Wch, out);
    phase3_kernel<<<NB * NT, 128>>>(dW1, db1, dW2, db2, dW3, db3, osc, obi, out);
}

// round 14
// speedup vs baseline: 1.1990x; 1.0735x over previous
#include <cuda_runtime.h>
#include <math.h>

#define NB 64
#define NT 128
#define NN 64
#define NC 128
#define NH 64
#define NE 192
#define TP 68
#define PY 196   // natural Y/Hcat pitch (floats): conflict-free A-fragment loads
#define WP 104   // sWh pitch (u32): conflict-free B-fragment loads
#define GP 104   // sG pitch
#define HP 196   // phase2 Hcat pitch

// U[b,t,n,e] fp32 (biases included). 384 MiB.
static __device__ float g_U[(size_t)NB * NT * NN * NE];
// Pooled hidden means per (b,t). 2 MiB.
static __device__ float g_pool[(size_t)NB * NT * NH];
// tf32 lo-part of hidden-path weights, [k=192][e=192]. 147 KB (L2-resident).
static __device__ unsigned g_Wl[192 * 192];

__device__ __forceinline__ unsigned smem_u32(const void* p) {
    unsigned r;
    asm("{ .reg .u64 t; cvta.to.shared.u64 t, %1; cvt.u32.u64 %0, t; }" : "=r"(r) : "l"(p));
    return r;
}
__device__ __forceinline__ unsigned cluster_rank() {
    unsigned r; asm("mov.u32 %0, %%cluster_ctarank;" : "=r"(r)); return r;
}
__device__ __forceinline__ void st_peer_f2(unsigned laddr, unsigned peer, float a, float b) {
    unsigned raddr;
    asm volatile("mapa.shared::cluster.u32 %0, %1, %2;" : "=r"(raddr) : "r"(laddr), "r"(peer));
    asm volatile("st.shared::cluster.v2.f32 [%0], {%1, %2};" :: "r"(raddr), "f"(a), "f"(b) : "memory");
}
#define CLUSTER_ARRIVE() asm volatile("barrier.cluster.arrive.aligned;" ::: "memory")
#define CLUSTER_WAIT()   asm volatile("barrier.cluster.wait.aligned;" ::: "memory")
#define CLUSTER_SYNC() do { CLUSTER_ARRIVE(); CLUSTER_WAIT(); } while (0)

__device__ __forceinline__ float rcp_ap(float x) {
    float y; asm("rcp.approx.f32 %0, %1;" : "=f"(y) : "f"(x)); return y;
}
__device__ __forceinline__ float tanh_fast(float x) {
    return 1.0f - 2.0f * rcp_ap(1.0f + __expf(2.0f * x));
}
__device__ __forceinline__ float sig_fast(float x) {
    return rcp_ap(1.0f + __expf(-x));
}
__device__ __forceinline__ unsigned f2tf(float x) {
    unsigned u; asm("cvt.rna.tf32.f32 %0, %1;" : "=r"(u) : "f"(x)); return u;
}
__device__ __forceinline__ void mma_tf32(float c[4], const unsigned a[4],
                                         unsigned b0, unsigned b1) {
    asm volatile(
        "mma.sync.aligned.m16n8k8.row.col.f32.tf32.tf32.f32 "
        "{%0,%1,%2,%3}, {%4,%5,%6,%7}, {%8,%9}, {%0,%1,%2,%3};"
        : "+f"(c[0]), "+f"(c[1]), "+f"(c[2]), "+f"(c[3])
        : "r"(a[0]), "r"(a[1]), "r"(a[2]), "r"(a[3]), "r"(b0), "r"(b1));
}

// ---------------------------------------------------------------------------
// prep2: tf32 lo-part of hidden weights, layout [k][e], e = gate*64+dc.
// ---------------------------------------------------------------------------
__global__ void prep2_kernel(const float* __restrict__ Wfh, const float* __restrict__ Wgh,
                             const float* __restrict__ Wch) {
    int i = blockIdx.x * 256 + threadIdx.x;
    if (i >= 36864) return;
    int k = i / 192, e = i % 192;
    int hop = k >> 6, dm = k & 63;
    int gate = e >> 6, dc = e & 63;
    const float* W = (gate == 0) ? Wfh : ((gate == 1) ? Wgh : Wch);
    float w = W[hop * 4096 + dm * 64 + dc];
    unsigned hi = f2tf(w);
    g_Wl[i] = f2tf(w - __uint_as_float(hi));
}

// ---------------------------------------------------------------------------
// Phase 1 (R13, passing): scalar encode + A-hops, tf32 mma gate-GEMM.
// grid 8192, block 256, 2 CTAs/SM. smem = 102400 B.
// ---------------------------------------------------------------------------
__global__ void __launch_bounds__(256, 2) phase1_kernel(
    const float* __restrict__ frames, const float* __restrict__ adj,
    const float* __restrict__ encW, const float* __restrict__ encB,
    const float* __restrict__ Wfu, const float* __restrict__ Wgu, const float* __restrict__ Wcu,
    const float* __restrict__ bf, const float* __restrict__ bg, const float* __restrict__ bc)
{
    extern __shared__ float sm[];
    float* sAT = sm;               // 4352
    float* sXT = sm + 4352;        // 4352
    float* sYT = sm + 8704;        // 4352
    float* sY  = sm + 13056;       // 64 x PY: 12544

    const int tid = threadIdx.x;
    const int bt = blockIdx.x;
    const float* fr = frames + (size_t)bt * (NC * NN);
    const float* Ap = adj + (size_t)bt * (NN * NN);

    for (int i = tid; i < NN * NN; i += 256)
        sAT[(i & 63) * TP + (i >> 6)] = Ap[i];
    __syncthreads();

    const int n0 = (tid & 15) * 4;
    const int d0 = (tid >> 4) * 4;

    float acc[4][4];
    {
#pragma unroll
        for (int i = 0; i < 4; i++)
#pragma unroll
            for (int j = 0; j < 4; j++) acc[i][j] = 0.f;
#pragma unroll 4
        for (int c = 0; c < NC; c++) {
            float4 a4 = __ldg((const float4*)&fr[c * 64 + n0]);
            float4 w4 = __ldg((const float4*)&encW[c * 64 + d0]);
            float av[4] = {a4.x, a4.y, a4.z, a4.w};
            float wv[4] = {w4.x, w4.y, w4.z, w4.w};
#pragma unroll
            for (int i = 0; i < 4; i++)
#pragma unroll
                for (int j = 0; j < 4; j++) acc[i][j] += wv[i] * av[j];
        }
        float4 b4 = __ldg((const float4*)&encB[d0]);
        float bv[4] = {b4.x, b4.y, b4.z, b4.w};
#pragma unroll
        for (int i = 0; i < 4; i++)
#pragma unroll
            for (int j = 0; j < 4; j++) acc[i][j] += bv[i];
#pragma unroll
        for (int i = 0; i < 4; i++)
            *(float4*)&sXT[(d0 + i) * TP + n0] =
                make_float4(acc[i][0], acc[i][1], acc[i][2], acc[i][3]);
#pragma unroll
        for (int j = 0; j < 4; j++)
            *(float4*)&sY[(n0 + j) * PY + d0] =
                make_float4(acc[0][j], acc[1][j], acc[2][j], acc[3][j]);
    }
    __syncthreads();

    {
#pragma unroll
        for (int i = 0; i < 4; i++)
#pragma unroll
            for (int j = 0; j < 4; j++) acc[i][j] = 0.f;
#pragma unroll 4
        for (int m = 0; m < 64; m++) {
            float4 a4 = *(const float4*)&sAT[m * TP + n0];
            float av[4] = {a4.x, a4.y, a4.z, a4.w};
            float p[4];
#pragma unroll
            for (int i = 0; i < 4; i++) p[i] = sXT[(d0 + i) * TP + m];
#pragma unroll
            for (int i = 0; i < 4; i++)
#pragma unroll
                for (int j = 0; j < 4; j++) acc[i][j] += p[i] * av[j];
        }
#pragma unroll
        for (int i = 0; i < 4; i++)
            *(float4*)&sYT[(d0 + i) * TP + n0] =
                make_float4(acc[i][0], acc[i][1], acc[i][2], acc[i][3]);
#pragma unroll
        for (int j = 0; j < 4; j++)
            *(float4*)&sY[(n0 + j) * PY + 64 + d0] =
                make_float4(acc[0][j], acc[1][j], acc[2][j], acc[3][j]);
    }
    __syncthreads();

    {
#pragma unroll
        for (int i = 0; i < 4; i++)
#pragma unroll
            for (int j = 0; j < 4; j++) acc[i][j] = 0.f;
#pragma unroll 4
        for (int m = 0; m < 64; m++) {
            float4 a4 = *(const float4*)&sAT[m * TP + n0];
            float av[4] = {a4.x, a4.y, a4.z, a4.w};
            float p[4];
#pragma unroll
            for (int i = 0; i < 4; i++) p[i] = sYT[(d0 + i) * TP + m];
#pragma unroll
            for (int i = 0; i < 4; i++)
#pragma unroll
                for (int j = 0; j < 4; j++) acc[i][j] += p[i] * av[j];
        }
#pragma unroll
        for (int j = 0; j < 4; j++)
            *(float4*)&sY[(n0 + j) * PY + 128 + d0] =
                make_float4(acc[0][j], acc[1][j], acc[2][j], acc[3][j]);
    }
    __syncthreads();

    const int w = tid >> 5;
    const int lane = tid & 31;
    const int g = lane >> 2;
    const int t4 = lane & 3;
    const int e0 = w * 24;

    const float* Wp[3];
    const float* Bp[3];
    int dcn[3];
#pragma unroll
    for (int nt = 0; nt < 3; nt++) {
        int e = e0 + nt * 8;
        int gate = e >> 6;
        dcn[nt] = e & 63;
        Wp[nt] = (gate == 0) ? Wfu : ((gate == 1) ? Wgu : Wcu);
        Bp[nt] = (gate == 0) ? bf  : ((gate == 1) ? bg  : bc);
    }

    float cacc[4][3][4];
#pragma unroll
    for (int nt = 0; nt < 3; nt++) {
        float b0v = __ldg(Bp[nt] + dcn[nt] + 2 * t4);
        float b1v = __ldg(Bp[nt] + dcn[nt] + 2 * t4 + 1);
#pragma unroll
        for (int mt = 0; mt < 4; mt++) {
            cacc[mt][nt][0] = b0v; cacc[mt][nt][1] = b1v;
            cacc[mt][nt][2] = b0v; cacc[mt][nt][3] = b1v;
        }
    }

#pragma unroll 1
    for (int kt = 0; kt < 24; kt++) {
        const int hop = kt >> 3;
        const int dk0 = (kt & 7) * 8;
        const int kc = kt * 8;

        float afv[4][4];
        unsigned ah[4][4];
#pragma unroll
        for (int mt = 0; mt < 4; mt++) {
            int r0 = (mt * 16 + g) * PY;
            int r1 = r0 + 8 * PY;
            afv[mt][0] = sY[r0 + kc + t4];
            afv[mt][1] = sY[r1 + kc + t4];
            afv[mt][2] = sY[r0 + kc + t4 + 4];
            afv[mt][3] = sY[r1 + kc + t4 + 4];
#pragma unroll
            for (int q = 0; q < 4; q++) ah[mt][q] = f2tf(afv[mt][q]);
        }

        unsigned bh[3][2];
#pragma unroll
        for (int nt = 0; nt < 3; nt++) {
            const float* W = Wp[nt];
            int base = hop * 4096 + (dk0 + t4) * 64 + dcn[nt] + g;
            float w0 = __ldg(W + base);
            float w1 = __ldg(W + base + 256);
            bh[nt][0] = f2tf(w0);
            bh[nt][1] = f2tf(w1);
            unsigned bl0 = f2tf(w0 - __uint_as_float(bh[nt][0]));
            unsigned bl1 = f2tf(w1 - __uint_as_float(bh[nt][1]));
#pragma unroll
            for (int mt = 0; mt < 4; mt++) {
                mma_tf32(cacc[mt][nt], ah[mt], bh[nt][0], bh[nt][1]);
                mma_tf32(cacc[mt][nt], ah[mt], bl0, bl1);
            }
        }

        unsigned al[4][4];
#pragma unroll
        for (int mt = 0; mt < 4; mt++)
#pragma unroll
            for (int q = 0; q < 4; q++)
                al[mt][q] = f2tf(afv[mt][q] - __uint_as_float(ah[mt][q]));
#pragma unroll
        for (int nt = 0; nt < 3; nt++)
#pragma unroll
            for (int mt = 0; mt < 4; mt++)
                mma_tf32(cacc[mt][nt], al[mt], bh[nt][0], bh[nt][1]);
    }

    float* Ub = g_U + (size_t)bt * (NN * NE);
#pragma unroll
    for (int mt = 0; mt < 4; mt++) {
        int row = mt * 16 + g;
#pragma unroll
        for (int nt = 0; nt < 3; nt++) {
            int col = e0 + nt * 8 + 2 * t4;
            *(float2*)&Ub[row * NE + col] = make_float2(cacc[mt][nt][0], cacc[mt][nt][1]);
            *(float2*)&Ub[(row + 8) * NE + col] = make_float2(cacc[mt][nt][2], cacc[mt][nt][3]);
        }
    }
}

// ---------------------------------------------------------------------------
// Phase 2: e/d-split cluster recurrence with tf32 mma gates.
// grid 128 (64 clusters of 2), block 512. smem = 174080 B.
// CTA rank owns d in [rank*32, rank*32+32) for all 3 gates.
// ---------------------------------------------------------------------------
__global__ void __launch_bounds__(512, 1) __cluster_dims__(2, 1, 1) phase2_kernel(
    const float* __restrict__ adj, const float* __restrict__ h0,
    const float* __restrict__ Wfh, const float* __restrict__ Wgh, const float* __restrict__ Wch,
    float* __restrict__ out)
{
    extern __shared__ char smc[];
    unsigned* sWh = (unsigned*)smc;              // 192 x WP u32: 79872
    float* sH  = (float*)(smc + 79872);          // 64 x HP: Hcat [n][hop*64+d]: 50176
    float* sAT = (float*)(smc + 130048);         // 64 x TP transposed A: 17408
    float* sG  = (float*)(smc + 147456);         // 64 x GP gate preacts: 26624

    const int tid = threadIdx.x;
    const int b = blockIdx.x >> 1;
    const unsigned rank = cluster_rank();
    const unsigned peer = rank ^ 1u;
    const int dbase = (int)rank * 32;

    // Stage Wh (own 96 e-cols, tf32)
    for (int i = tid; i < 192 * 96; i += 512) {
        int k = i / 96, ep = i % 96;
        int gate = ep >> 5, dloc = ep & 31;
        int hop = k >> 6, dm = k & 63;
        const float* W = (gate == 0) ? Wfh : ((gate == 1) ? Wgh : Wch);
        sWh[k * WP + ep] = f2tf(W[hop * 4096 + dm * 64 + dbase + dloc]);
    }
    // Stage h0 full
    for (int i = tid; i < 4096; i += 512) {
        int n = i >> 6, d = i & 63;
        sH[n * HP + d] = h0[b * 4096 + i];
    }
    __syncthreads();
    CLUSTER_SYNC();
    CLUSTER_ARRIVE();   // pre-arm: loop starts with WAIT

    const unsigned u_sH = smem_u32(sH);

    // mm / h_new mapping: 2n x 2d-local per thread
    const int mn0 = (tid >> 4) * 2;   // n (0..62)
    const int mdl = (tid & 15) * 2;   // d-local (0..30)

    // mma mapping
    const int w = tid >> 5, lane = tid & 31;
    const int g = lane >> 2, t4 = lane & 3;
    const int mt = w & 3, ng = w >> 2;
    const int r0 = mt * 16 + g;
    int epb[3], egl[3];
#pragma unroll
    for (int nt = 0; nt < 3; nt++) {
        epb[nt] = (ng * 3 + nt) * 8;
        int gate = epb[nt] >> 5;
        egl[nt] = gate * 64 + dbase + (epb[nt] & 31);
    }

    // U prefetch (step 0)
    float2 pu[6];
    {
        const float* Ub = g_U + ((size_t)(b * NT)) * (NN * NE);
#pragma unroll
        for (int nt = 0; nt < 3; nt++) {
            pu[nt * 2]     = *(const float2*)&Ub[r0 * NE + egl[nt] + 2 * t4];
            pu[nt * 2 + 1] = *(const float2*)&Ub[(r0 + 8) * NE + egl[nt] + 2 * t4];
        }
    }

    for (int t = 0; t < NT; t++) {
        CLUSTER_WAIT();   // Hcat hop0 = h(t) full (peer h_new pushes of t-1)

        // accumulators from prefetched U
        float c[3][4];
#pragma unroll
        for (int nt = 0; nt < 3; nt++) {
            c[nt][0] = pu[nt * 2].x;     c[nt][1] = pu[nt * 2].y;
            c[nt][2] = pu[nt * 2 + 1].x; c[nt][3] = pu[nt * 2 + 1].y;
        }
        // prefetch U(t+1)
        {
            int btn = b * NT + t + 1;
            if (btn > NB * NT - 1) btn = NB * NT - 1;
            const float* Ub = g_U + (size_t)btn * (NN * NE);
#pragma unroll
            for (int nt = 0; nt < 3; nt++) {
                pu[nt * 2]     = *(const float2*)&Ub[r0 * NE + egl[nt] + 2 * t4];
                pu[nt * 2 + 1] = *(const float2*)&Ub[(r0 + 8) * NE + egl[nt] + 2 * t4];
            }
        }
        // pool of h(t) = h_new(t-1) -> g_pool[t-1]
        if (rank == 0 && t > 0) {
            int d = tid >> 3, q = tid & 7;
            float s = 0.f;
#pragma unroll
            for (int nn = 0; nn < 8; nn++) s += sH[(q * 8 + nn) * HP + d];
            s += __shfl_xor_sync(0xFFFFFFFFu, s, 1);
            s += __shfl_xor_sync(0xFFFFFFFFu, s, 2);
            s += __shfl_xor_sync(0xFFFFFFFFu, s, 4);
            if (q == 0)
                g_pool[((size_t)(b * NT + t - 1)) * NH + d] = s * (1.0f / 64.0f);
        }
        // stage adjacency transposed
        {
            const float* Ap = adj + ((size_t)(b * NT + t)) * 4096;
            for (int i = tid; i < 4096; i += 512) {
                int n = i >> 6, m = i & 63;
                sAT[m * TP + n] = Ap[i];
            }
        }
        __syncthreads();   // sAT ready

        // mm1: h1[n][d-own] = A h(:, d-own)  (exact fp32, local)
        {
            float mv[2][2] = {{0.f, 0.f}, {0.f, 0.f}};
#pragma unroll 4
            for (int m = 0; m < 64; m++) {
                float2 a2 = *(const float2*)&sAT[m * TP + mn0];
                float2 p  = *(const float2*)&sH[m * HP + dbase + mdl];
                mv[0][0] += a2.x * p.x;  mv[0][1] += a2.x * p.y;
                mv[1][0] += a2.y * p.x;  mv[1][1] += a2.y * p.y;
            }
#pragma unroll
            for (int i = 0; i < 2; i++) {
                int off = (mn0 + i) * HP + 64 + dbase + mdl;
                *(float2*)&sH[off] = make_float2(mv[i][0], mv[i][1]);
                st_peer_f2(u_sH + (unsigned)off * 4u, peer, mv[i][0], mv[i][1]);
            }
        }
        CLUSTER_ARRIVE();

        // gates hop0 (K 0..63) — Hcat hop0 stable
#pragma unroll 2
        for (int kt = 0; kt < 8; kt++) {
            int kg = kt * 8;
            float a0f = sH[r0 * HP + kg + t4];
            float a1f = sH[(r0 + 8) * HP + kg + t4];
            float a2f = sH[r0 * HP + kg + t4 + 4];
            float a3f = sH[(r0 + 8) * HP + kg + t4 + 4];
            unsigned ah[4] = {f2tf(a0f), f2tf(a1f), f2tf(a2f), f2tf(a3f)};
            unsigned al[4] = {f2tf(a0f - __uint_as_float(ah[0])),
                              f2tf(a1f - __uint_as_float(ah[1])),
                              f2tf(a2f - __uint_as_float(ah[2])),
                              f2tf(a3f - __uint_as_float(ah[3]))};
#pragma unroll
            for (int nt = 0; nt < 3; nt++) {
                unsigned bh0 = sWh[(kg + t4) * WP + epb[nt] + g];
                unsigned bh1 = sWh[(kg + t4 + 4) * WP + epb[nt] + g];
                unsigned bl0 = __ldg(&g_Wl[(kg + t4) * 192 + egl[nt] + g]);
                unsigned bl1 = __ldg(&g_Wl[(kg + t4 + 4) * 192 + egl[nt] + g]);
                mma_tf32(c[nt], ah, bh0, bh1);
                mma_tf32(c[nt], al, bh0, bh1);
                mma_tf32(c[nt], ah, bl0, bl1);
            }
        }

        CLUSTER_WAIT();    // h1 full
        __syncthreads();   // local mm1 writes visible

        // mm2: h2[n][d-own] = A h1(:, d-own)
        {
            float mv[2][2] = {{0.f, 0.f}, {0.f, 0.f}};
#pragma unroll 4
            for (int m = 0; m < 64; m++) {
                float2 a2 = *(const float2*)&sAT[m * TP + mn0];
                float2 p  = *(const float2*)&sH[m * HP + 64 + dbase + mdl];
                mv[0][0] += a2.x * p.x;  mv[0][1] += a2.x * p.y;
                mv[1][0] += a2.y * p.x;  mv[1][1] += a2.y * p.y;
            }
#pragma unroll
            for (int i = 0; i < 2; i++) {
                int off = (mn0 + i) * HP + 128 + dbase + mdl;
                *(float2*)&sH[off] = make_float2(mv[i][0], mv[i][1]);
                st_peer_f2(u_sH + (unsigned)off * 4u, peer, mv[i][0], mv[i][1]);
            }
        }
        CLUSTER_ARRIVE();

        // gates hop1 (K 64..127) — h1 full
#pragma unroll 2
        for (int kt = 0; kt < 8; kt++) {
            int kg = 64 + kt * 8;
            float a0f = sH[r0 * HP + kg + t4];
            float a1f = sH[(r0 + 8) * HP + kg + t4];
            float a2f = sH[r0 * HP + kg + t4 + 4];
            float a3f = sH[(r0 + 8) * HP + kg + t4 + 4];
            unsigned ah[4] = {f2tf(a0f), f2tf(a1f), f2tf(a2f), f2tf(a3f)};
            unsigned al[4] = {f2tf(a0f - __uint_as_float(ah[0])),
                              f2tf(a1f - __uint_as_float(ah[1])),
                              f2tf(a2f - __uint_as_float(ah[2])),
                              f2tf(a3f - __uint_as_float(ah[3]))};
#pragma unroll
            for (int nt = 0; nt < 3; nt++) {
                unsigned bh0 = sWh[(kg + t4) * WP + epb[nt] + g];
                unsigned bh1 = sWh[(kg + t4 + 4) * WP + epb[nt] + g];
                unsigned bl0 = __ldg(&g_Wl[(kg + t4) * 192 + egl[nt] + g]);
                unsigned bl1 = __ldg(&g_Wl[(kg + t4 + 4) * 192 + egl[nt] + g]);
                mma_tf32(c[nt], ah, bh0, bh1);
                mma_tf32(c[nt], al, bh0, bh1);
                mma_tf32(c[nt], ah, bl0, bl1);
            }
        }

        CLUSTER_WAIT();    // h2 full
        __syncthreads();   // local mm2 writes visible

        // gates hop2 (K 128..191)
#pragma unroll 2
        for (int kt = 0; kt < 8; kt++) {
            int kg = 128 + kt * 8;
            float a0f = sH[r0 * HP + kg + t4];
            float a1f = sH[(r0 + 8) * HP + kg + t4];
            float a2f = sH[r0 * HP + kg + t4 + 4];
            float a3f = sH[(r0 + 8) * HP + kg + t4 + 4];
            unsigned ah[4] = {f2tf(a0f), f2tf(a1f), f2tf(a2f), f2tf(a3f)};
            unsigned al[4] = {f2tf(a0f - __uint_as_float(ah[0])),
                              f2tf(a1f - __uint_as_float(ah[1])),
                              f2tf(a2f - __uint_as_float(ah[2])),
                              f2tf(a3f - __uint_as_float(ah[3]))};
#pragma unroll
            for (int nt = 0; nt < 3; nt++) {
                unsigned bh0 = sWh[(kg + t4) * WP + epb[nt] + g];
                unsigned bh1 = sWh[(kg + t4 + 4) * WP + epb[nt] + g];
                unsigned bl0 = __ldg(&g_Wl[(kg + t4) * 192 + egl[nt] + g]);
                unsigned bl1 = __ldg(&g_Wl[(kg + t4 + 4) * 192 + egl[nt] + g]);
                mma_tf32(c[nt], ah, bh0, bh1);
                mma_tf32(c[nt], al, bh0, bh1);
                mma_tf32(c[nt], ah, bl0, bl1);
            }
        }

        // store G tiles to sG
#pragma unroll
        for (int nt = 0; nt < 3; nt++) {
            int col = epb[nt] + 2 * t4;
            *(float2*)&sG[r0 * GP + col] = make_float2(c[nt][0], c[nt][1]);
            *(float2*)&sG[(r0 + 8) * GP + col] = make_float2(c[nt][2], c[nt][3]);
        }
        __syncthreads();   // sG complete

        // nonlinearity -> h_new own d-cols; write local + push peer
#pragma unroll
        for (int i = 0; i < 2; i++) {
            int row = mn0 + i;
            float hv[2];
#pragma unroll
            for (int j = 0; j < 2; j++) {
                float fv = sG[row * GP + mdl + j];
                float gv = sG[row * GP + 32 + mdl + j];
                float cv = sG[row * GP + 64 + mdl + j];
                float f = sig_fast(fv);
                float tg = tanh_fast(gv);
                float tc = tanh_fast(cv);
                hv[j] = f * (tg - tc) + tc;
            }
            int off = row * HP + dbase + mdl;
            *(float2*)&sH[off] = make_float2(hv[0], hv[1]);
            st_peer_f2(u_sH + (unsigned)off * 4u, peer, hv[0], hv[1]);
        }
        CLUSTER_ARRIVE();
    }

    CLUSTER_WAIT();   // final h full

    if (rank == 0) {
        {
            int d = tid >> 3, q = tid & 7;
            float s = 0.f;
#pragma unroll
            for (int nn = 0; nn < 8; nn++) s += sH[(q * 8 + nn) * HP + d];
            s += __shfl_xor_sync(0xFFFFFFFFu, s, 1);
            s += __shfl_xor_sync(0xFFFFFFFFu, s, 2);
            s += __shfl_xor_sync(0xFFFFFFFFu, s, 4);
            if (q == 0)
                g_pool[((size_t)(b * NT + NT - 1)) * NH + d] = s * (1.0f / 64.0f);
        }
        float* fh = out + (size_t)NB * NT * 6 + (size_t)b * (NN * NH);
        for (int i = tid; i < 4096; i += 512)
            fh[i] = sH[(i >> 6) * HP + (i & 63)];
    }
}

// ---------------------------------------------------------------------------
// Phase 3: decoder MLP per (b,t). grid 8192, block 128.
// ---------------------------------------------------------------------------
__global__ void __launch_bounds__(128, 8) phase3_kernel(
    const float* __restrict__ dW1, const float* __restrict__ db1,
    const float* __restrict__ dW2, const float* __restrict__ db2,
    const float* __restrict__ dW3, const float* __restrict__ db3,
    const float* __restrict__ osc, const float* __restrict__ obi,
    float* __restrict__ out)
{
    __shared__ float sp[64];
    __shared__ float z1[128];
    __shared__ float z2[64];
    const int bt = blockIdx.x;
    const int tid = threadIdx.x;

    if (tid < 64) sp[tid] = g_pool[(size_t)bt * NH + tid];
    __syncthreads();
    {
        float a = db1[tid];
#pragma unroll 4
        for (int d = 0; d < 64; d++) a += sp[d] * dW1[d * 128 + tid];
        z1[tid] = fmaxf(a, 0.f);
    }
    __syncthreads();
    if (tid < 64) {
        float a = db2[tid];
#pragma unroll 4
        for (int i = 0; i < 128; i++) a += z1[i] * dW2[i * 64 + tid];
        z2[tid] = fmaxf(a, 0.f);
    }
    __syncthreads();
    if (tid < 6) {
        float a = db3[tid];
#pragma unroll 4
        for (int j = 0; j < 64; j++) a += z2[j] * dW3[j * 6 + tid];
        out[(size_t)bt * 6 + tid] = a * osc[tid] + obi[tid];
    }
}

extern "C" void kernel_launch(void* const* d_in, const int* in_sizes, int n_in,
                              void* d_out, int out_size) {
    const float* frames = (const float*)d_in[0];
    const float* adj    = (const float*)d_in[1];
    const float* h0     = (const float*)d_in[2];
    const float* encW   = (const float*)d_in[3];
    const float* encB   = (const float*)d_in[4];
    const float* Wfh    = (const float*)d_in[5];
    const float* Wfu    = (const float*)d_in[6];
    const float* bf     = (const float*)d_in[7];
    const float* Wgh    = (const float*)d_in[8];
    const float* Wgu    = (const float*)d_in[9];
    const float* bg     = (const float*)d_in[10];
    const float* Wch    = (const float*)d_in[11];
    const float* Wcu    = (const float*)d_in[12];
    const float* bc     = (const float*)d_in[13];
    const float* dW1    = (const float*)d_in[14];
    const float* db1    = (const float*)d_in[15];
    const float* dW2    = (const float*)d_in[16];
    const float* db2    = (const float*)d_in[17];
    const float* dW3    = (const float*)d_in[18];
    const float* db3    = (const float*)d_in[19];
    const float* osc    = (const float*)d_in[20];
    const float* obi    = (const float*)d_in[21];
    float* out = (float*)d_out;

    const int smem1 = 25600 * 4;   // 102400 B -> 2 CTAs/SM
    const int smem2 = 174080;      // phase-2 e/d-split tensor kernel
    cudaFuncSetAttribute(phase1_kernel, cudaFuncAttributeMaxDynamicSharedMemorySize, smem1);
    cudaFuncSetAttribute(phase2_kernel, cudaFuncAttributeMaxDynamicSharedMemorySize, smem2);

    prep2_kernel<<<144, 256>>>(Wfh, Wgh, Wch);
    phase1_kernel<<<NB * NT, 256, smem1>>>(frames, adj, encW, encB,
                                           Wfu, Wgu, Wcu, bf, bg, bc);
    phase2_kernel<<<NB * 2, 512, smem2>>>(adj, h0, Wfh, Wgh, Wch, out);
    phase3_kernel<<<NB * NT, 128>>>(dW1, db1, dW2, db2, dW3, db3, osc, obi, out);
}

// round 15
// speedup vs baseline: 1.2611x; 1.0519x over previous
#include <cuda_runtime.h>
#include <math.h>

#define NB 64
#define NT 128
#define NN 64
#define NC 128
#define NH 64
#define NE 192
#define TP 68
#define WP 104   // phase2 sWh pitch (u32)
#define GP 104   // phase2 sG pitch
#define HP 196   // phase2 Hcat pitch
#define PB 68    // phase1 buffer pitch (A-frag conflict-free)

// U[b,t,n,e] fp32 (biases included). 384 MiB.
static __device__ float g_U[(size_t)NB * NT * NN * NE];
// Pooled hidden means per (b,t). 2 MiB.
static __device__ float g_pool[(size_t)NB * NT * NH];
// tf32 lo-part of hidden-path weights, [k=192][e=192]. 147 KB (L2-resident).
static __device__ unsigned g_Wl[192 * 192];

__device__ __forceinline__ unsigned smem_u32(const void* p) {
    unsigned r;
    asm("{ .reg .u64 t; cvta.to.shared.u64 t, %1; cvt.u32.u64 %0, t; }" : "=r"(r) : "l"(p));
    return r;
}
__device__ __forceinline__ unsigned cluster_rank() {
    unsigned r; asm("mov.u32 %0, %%cluster_ctarank;" : "=r"(r)); return r;
}
__device__ __forceinline__ void st_peer_f2(unsigned laddr, unsigned peer, float a, float b) {
    unsigned raddr;
    asm volatile("mapa.shared::cluster.u32 %0, %1, %2;" : "=r"(raddr) : "r"(laddr), "r"(peer));
    asm volatile("st.shared::cluster.v2.f32 [%0], {%1, %2};" :: "r"(raddr), "f"(a), "f"(b) : "memory");
}
#define CLUSTER_ARRIVE() asm volatile("barrier.cluster.arrive.aligned;" ::: "memory")
#define CLUSTER_WAIT()   asm volatile("barrier.cluster.wait.aligned;" ::: "memory")
#define CLUSTER_SYNC() do { CLUSTER_ARRIVE(); CLUSTER_WAIT(); } while (0)

__device__ __forceinline__ float rcp_ap(float x) {
    float y; asm("rcp.approx.f32 %0, %1;" : "=f"(y) : "f"(x)); return y;
}
__device__ __forceinline__ float tanh_fast(float x) {
    return 1.0f - 2.0f * rcp_ap(1.0f + __expf(2.0f * x));
}
__device__ __forceinline__ float sig_fast(float x) {
    return rcp_ap(1.0f + __expf(-x));
}
__device__ __forceinline__ unsigned f2tf(float x) {
    unsigned u; asm("cvt.rna.tf32.f32 %0, %1;" : "=r"(u) : "f"(x)); return u;
}
__device__ __forceinline__ void mma_tf32(float c[4], const unsigned a[4],
                                         unsigned b0, unsigned b1) {
    asm volatile(
        "mma.sync.aligned.m16n8k8.row.col.f32.tf32.tf32.f32 "
        "{%0,%1,%2,%3}, {%4,%5,%6,%7}, {%8,%9}, {%0,%1,%2,%3};"
        : "+f"(c[0]), "+f"(c[1]), "+f"(c[2]), "+f"(c[3])
        : "r"(a[0]), "r"(a[1]), "r"(a[2]), "r"(a[3]), "r"(b0), "r"(b1));
}

// ---------------------------------------------------------------------------
// prep2: tf32 lo-part of hidden weights, layout [k][e], e = gate*64+dc.
// ---------------------------------------------------------------------------
__global__ void prep2_kernel(const float* __restrict__ Wfh, const float* __restrict__ Wgh,
                             const float* __restrict__ Wch) {
    int i = blockIdx.x * 256 + threadIdx.x;
    if (i >= 36864) return;
    int k = i / 192, e = i % 192;
    int hop = k >> 6, dm = k & 63;
    int gate = e >> 6, dc = e & 63;
    const float* W = (gate == 0) ? Wfh : ((gate == 1) ? Wgh : Wch);
    float w = W[hop * 4096 + dm * 64 + dc];
    unsigned hi = f2tf(w);
    g_Wl[i] = f2tf(w - __uint_as_float(hi));
}

// ---------------------------------------------------------------------------
// Phase 1 (ALL tensor): encode + A-hops + gate GEMM via 3xTF32 mma.sync.
// grid 8192, block 256, 2 CTAs/SM. smem = 69632 B.
// ---------------------------------------------------------------------------
// one mm: dst[n][d] = A @ src  (A = sAN natural [n][m] pitch PB, src [m][d] pitch PB)
__device__ __forceinline__ void mm_mma(float* __restrict__ dst,
                                       const float* __restrict__ sAN,
                                       const float* __restrict__ src,
                                       int g, int t4, int col0)
{
    float cm[4][4];
#pragma unroll
    for (int mt = 0; mt < 4; mt++)
#pragma unroll
        for (int q = 0; q < 4; q++) cm[mt][q] = 0.f;

#pragma unroll 1
    for (int kc = 0; kc < 8; kc++) {
        int k0 = kc * 8;
        // B frags (src) hi/lo
        float x0 = src[(k0 + t4) * PB + col0 + g];
        float x1 = src[(k0 + t4 + 4) * PB + col0 + g];
        unsigned bh0 = f2tf(x0), bh1 = f2tf(x1);
        unsigned bl0 = f2tf(x0 - __uint_as_float(bh0));
        unsigned bl1 = f2tf(x1 - __uint_as_float(bh1));
#pragma unroll
        for (int mt = 0; mt < 4; mt++) {
            int r0 = mt * 16 + g;
            float a0f = sAN[r0 * PB + k0 + t4];
            float a1f = sAN[(r0 + 8) * PB + k0 + t4];
            float a2f = sAN[r0 * PB + k0 + t4 + 4];
            float a3f = sAN[(r0 + 8) * PB + k0 + t4 + 4];
            unsigned ah[4] = {f2tf(a0f), f2tf(a1f), f2tf(a2f), f2tf(a3f)};
            unsigned al[4] = {f2tf(a0f - __uint_as_float(ah[0])),
                              f2tf(a1f - __uint_as_float(ah[1])),
                              f2tf(a2f - __uint_as_float(ah[2])),
                              f2tf(a3f - __uint_as_float(ah[3]))};
            mma_tf32(cm[mt], ah, bh0, bh1);
            mma_tf32(cm[mt], al, bh0, bh1);
            mma_tf32(cm[mt], ah, bl0, bl1);
        }
    }
#pragma unroll
    for (int mt = 0; mt < 4; mt++) {
        int r0 = mt * 16 + g;
        *(float2*)&dst[r0 * PB + col0 + 2 * t4] = make_float2(cm[mt][0], cm[mt][1]);
        *(float2*)&dst[(r0 + 8) * PB + col0 + 2 * t4] = make_float2(cm[mt][2], cm[mt][3]);
    }
}

__global__ void __launch_bounds__(256, 2) phase1_kernel(
    const float* __restrict__ frames, const float* __restrict__ adj,
    const float* __restrict__ encW, const float* __restrict__ encB,
    const float* __restrict__ Wfu, const float* __restrict__ Wgu, const float* __restrict__ Wcu,
    const float* __restrict__ bf, const float* __restrict__ bg, const float* __restrict__ bc)
{
    extern __shared__ float sm[];
    float* sAN = sm;               // A natural [n][m] pitch PB: 4352 floats
    float* sX  = sm + 4352;        // x  [m][d]
    float* sY1 = sm + 8704;        // y1 [m][d]
    float* sY2 = sm + 13056;       // y2 [m][d]

    const int tid = threadIdx.x;
    const int bt = blockIdx.x;
    const float* fr = frames + (size_t)bt * (NC * NN);
    const float* Ap = adj + (size_t)bt * (NN * NN);

    // stage A natural
    for (int i = tid; i < NN * NN; i += 256) {
        int n = i >> 6, m = i & 63;
        sAN[n * PB + m] = Ap[i];
    }

    const int w = tid >> 5;
    const int lane = tid & 31;
    const int g = lane >> 2;
    const int t4 = lane & 3;
    const int col0 = w * 8;      // d-tile for encode/mms

    // ---------- encode: x[n][d] = fr^T @ encW + encB  (M64 N64 K128)
    {
        float ce[4][4];
        {
            float b0v = __ldg(&encB[col0 + 2 * t4]);
            float b1v = __ldg(&encB[col0 + 2 * t4 + 1]);
#pragma unroll
            for (int mt = 0; mt < 4; mt++) {
                ce[mt][0] = b0v; ce[mt][1] = b1v;
                ce[mt][2] = b0v; ce[mt][3] = b1v;
            }
        }
#pragma unroll 1
        for (int kc = 0; kc < 16; kc++) {
            int k0 = kc * 8;
            float w0 = __ldg(&encW[(k0 + t4) * 64 + col0 + g]);
            float w1 = __ldg(&encW[(k0 + t4 + 4) * 64 + col0 + g]);
            unsigned bh0 = f2tf(w0), bh1 = f2tf(w1);
            unsigned bl0 = f2tf(w0 - __uint_as_float(bh0));
            unsigned bl1 = f2tf(w1 - __uint_as_float(bh1));
#pragma unroll
            for (int mt = 0; mt < 4; mt++) {
                int r0 = mt * 16 + g;
                float a0f = __ldg(&fr[(k0 + t4) * 64 + r0]);
                float a1f = __ldg(&fr[(k0 + t4) * 64 + r0 + 8]);
                float a2f = __ldg(&fr[(k0 + t4 + 4) * 64 + r0]);
                float a3f = __ldg(&fr[(k0 + t4 + 4) * 64 + r0 + 8]);
                unsigned ah[4] = {f2tf(a0f), f2tf(a1f), f2tf(a2f), f2tf(a3f)};
                unsigned al[4] = {f2tf(a0f - __uint_as_float(ah[0])),
                                  f2tf(a1f - __uint_as_float(ah[1])),
                                  f2tf(a2f - __uint_as_float(ah[2])),
                                  f2tf(a3f - __uint_as_float(ah[3]))};
                mma_tf32(ce[mt], ah, bh0, bh1);
                mma_tf32(ce[mt], al, bh0, bh1);
                mma_tf32(ce[mt], ah, bl0, bl1);
            }
        }
#pragma unroll
        for (int mt = 0; mt < 4; mt++) {
            int r0 = mt * 16 + g;
            *(float2*)&sX[r0 * PB + col0 + 2 * t4] = make_float2(ce[mt][0], ce[mt][1]);
            *(float2*)&sX[(r0 + 8) * PB + col0 + 2 * t4] = make_float2(ce[mt][2], ce[mt][3]);
        }
    }
    __syncthreads();   // sAN + sX ready

    mm_mma(sY1, sAN, sX, g, t4, col0);    // y1 = A x
    __syncthreads();
    mm_mma(sY2, sAN, sY1, g, t4, col0);   // y2 = A y1
    __syncthreads();

    // ---------- gate GEMM (R13 algebra): U = [x|y1|y2] @ Wcat + bias
    const int e0 = w * 24;
    const float* Wp[3];
    const float* Bp[3];
    int dcn[3];
#pragma unroll
    for (int nt = 0; nt < 3; nt++) {
        int e = e0 + nt * 8;
        int gate = e >> 6;
        dcn[nt] = e & 63;
        Wp[nt] = (gate == 0) ? Wfu : ((gate == 1) ? Wgu : Wcu);
        Bp[nt] = (gate == 0) ? bf  : ((gate == 1) ? bg  : bc);
    }

    float cacc[4][3][4];
#pragma unroll
    for (int nt = 0; nt < 3; nt++) {
        float b0v = __ldg(Bp[nt] + dcn[nt] + 2 * t4);
        float b1v = __ldg(Bp[nt] + dcn[nt] + 2 * t4 + 1);
#pragma unroll
        for (int mt = 0; mt < 4; mt++) {
            cacc[mt][nt][0] = b0v; cacc[mt][nt][1] = b1v;
            cacc[mt][nt][2] = b0v; cacc[mt][nt][3] = b1v;
        }
    }

    const float* bufs[3] = {sX, sY1, sY2};
#pragma unroll 1
    for (int kt = 0; kt < 24; kt++) {
        const int hop = kt >> 3;
        const int dk0 = (kt & 7) * 8;
        const float* Bf = bufs[hop];

        float afv[4][4];
        unsigned ah[4][4];
#pragma unroll
        for (int mt = 0; mt < 4; mt++) {
            int r0 = (mt * 16 + g) * PB;
            int r1 = r0 + 8 * PB;
            afv[mt][0] = Bf[r0 + dk0 + t4];
            afv[mt][1] = Bf[r1 + dk0 + t4];
            afv[mt][2] = Bf[r0 + dk0 + t4 + 4];
            afv[mt][3] = Bf[r1 + dk0 + t4 + 4];
#pragma unroll
            for (int q = 0; q < 4; q++) ah[mt][q] = f2tf(afv[mt][q]);
        }

        unsigned bh[3][2];
#pragma unroll
        for (int nt = 0; nt < 3; nt++) {
            const float* W = Wp[nt];
            int base = hop * 4096 + (dk0 + t4) * 64 + dcn[nt] + g;
            float w0 = __ldg(W + base);
            float w1 = __ldg(W + base + 256);
            bh[nt][0] = f2tf(w0);
            bh[nt][1] = f2tf(w1);
            unsigned bl0 = f2tf(w0 - __uint_as_float(bh[nt][0]));
            unsigned bl1 = f2tf(w1 - __uint_as_float(bh[nt][1]));
#pragma unroll
            for (int mt = 0; mt < 4; mt++) {
                mma_tf32(cacc[mt][nt], ah[mt], bh[nt][0], bh[nt][1]);
                mma_tf32(cacc[mt][nt], ah[mt], bl0, bl1);
            }
        }

        unsigned al[4][4];
#pragma unroll
        for (int mt = 0; mt < 4; mt++)
#pragma unroll
            for (int q = 0; q < 4; q++)
                al[mt][q] = f2tf(afv[mt][q] - __uint_as_float(ah[mt][q]));
#pragma unroll
        for (int nt = 0; nt < 3; nt++)
#pragma unroll
            for (int mt = 0; mt < 4; mt++)
                mma_tf32(cacc[mt][nt], al[mt], bh[nt][0], bh[nt][1]);
    }

    float* Ub = g_U + (size_t)bt * (NN * NE);
#pragma unroll
    for (int mt = 0; mt < 4; mt++) {
        int row = mt * 16 + g;
#pragma unroll
        for (int nt = 0; nt < 3; nt++) {
            int col = e0 + nt * 8 + 2 * t4;
            *(float2*)&Ub[row * NE + col] = make_float2(cacc[mt][nt][0], cacc[mt][nt][1]);
            *(float2*)&Ub[(row + 8) * NE + col] = make_float2(cacc[mt][nt][2], cacc[mt][nt][3]);
        }
    }
}

// ---------------------------------------------------------------------------
// Phase 2 (R14, passing): e/d-split cluster recurrence with tf32 mma gates.
// grid 128 (64 clusters of 2), block 512. smem = 174080 B.
// ---------------------------------------------------------------------------
__global__ void __launch_bounds__(512, 1) __cluster_dims__(2, 1, 1) phase2_kernel(
    const float* __restrict__ adj, const float* __restrict__ h0,
    const float* __restrict__ Wfh, const float* __restrict__ Wgh, const float* __restrict__ Wch,
    float* __restrict__ out)
{
    extern __shared__ char smc[];
    unsigned* sWh = (unsigned*)smc;              // 192 x WP u32: 79872
    float* sH  = (float*)(smc + 79872);          // 64 x HP: 50176
    float* sAT = (float*)(smc + 130048);         // 64 x TP: 17408
    float* sG  = (float*)(smc + 147456);         // 64 x GP: 26624

    const int tid = threadIdx.x;
    const int b = blockIdx.x >> 1;
    const unsigned rank = cluster_rank();
    const unsigned peer = rank ^ 1u;
    const int dbase = (int)rank * 32;

    for (int i = tid; i < 192 * 96; i += 512) {
        int k = i / 96, ep = i % 96;
        int gate = ep >> 5, dloc = ep & 31;
        int hop = k >> 6, dm = k & 63;
        const float* W = (gate == 0) ? Wfh : ((gate == 1) ? Wgh : Wch);
        sWh[k * WP + ep] = f2tf(W[hop * 4096 + dm * 64 + dbase + dloc]);
    }
    for (int i = tid; i < 4096; i += 512) {
        int n = i >> 6, d = i & 63;
        sH[n * HP + d] = h0[b * 4096 + i];
    }
    __syncthreads();
    CLUSTER_SYNC();
    CLUSTER_ARRIVE();

    const unsigned u_sH = smem_u32(sH);

    const int mn0 = (tid >> 4) * 2;
    const int mdl = (tid & 15) * 2;

    const int w = tid >> 5, lane = tid & 31;
    const int g = lane >> 2, t4 = lane & 3;
    const int mt = w & 3, ng = w >> 2;
    const int r0 = mt * 16 + g;
    int epb[3], egl[3];
#pragma unroll
    for (int nt = 0; nt < 3; nt++) {
        epb[nt] = (ng * 3 + nt) * 8;
        int gate = epb[nt] >> 5;
        egl[nt] = gate * 64 + dbase + (epb[nt] & 31);
    }

    float2 pu[6];
    {
        const float* Ub = g_U + ((size_t)(b * NT)) * (NN * NE);
#pragma unroll
        for (int nt = 0; nt < 3; nt++) {
            pu[nt * 2]     = *(const float2*)&Ub[r0 * NE + egl[nt] + 2 * t4];
            pu[nt * 2 + 1] = *(const float2*)&Ub[(r0 + 8) * NE + egl[nt] + 2 * t4];
        }
    }

    for (int t = 0; t < NT; t++) {
        CLUSTER_WAIT();

        float c[3][4];
#pragma unroll
        for (int nt = 0; nt < 3; nt++) {
            c[nt][0] = pu[nt * 2].x;     c[nt][1] = pu[nt * 2].y;
            c[nt][2] = pu[nt * 2 + 1].x; c[nt][3] = pu[nt * 2 + 1].y;
        }
        {
            int btn = b * NT + t + 1;
            if (btn > NB * NT - 1) btn = NB * NT - 1;
            const float* Ub = g_U + (size_t)btn * (NN * NE);
#pragma unroll
            for (int nt = 0; nt < 3; nt++) {
                pu[nt * 2]     = *(const float2*)&Ub[r0 * NE + egl[nt] + 2 * t4];
                pu[nt * 2 + 1] = *(const float2*)&Ub[(r0 + 8) * NE + egl[nt] + 2 * t4];
            }
        }
        if (rank == 0 && t > 0) {
            int d = tid >> 3, q = tid & 7;
            float s = 0.f;
#pragma unroll
            for (int nn = 0; nn < 8; nn++) s += sH[(q * 8 + nn) * HP + d];
            s += __shfl_xor_sync(0xFFFFFFFFu, s, 1);
            s += __shfl_xor_sync(0xFFFFFFFFu, s, 2);
            s += __shfl_xor_sync(0xFFFFFFFFu, s, 4);
            if (q == 0)
                g_pool[((size_t)(b * NT + t - 1)) * NH + d] = s * (1.0f / 64.0f);
        }
        {
            const float* Ap = adj + ((size_t)(b * NT + t)) * 4096;
            for (int i = tid; i < 4096; i += 512) {
                int n = i >> 6, m = i & 63;
                sAT[m * TP + n] = Ap[i];
            }
        }
        __syncthreads();

        {
            float mv[2][2] = {{0.f, 0.f}, {0.f, 0.f}};
#pragma unroll 4
            for (int m = 0; m < 64; m++) {
                float2 a2 = *(const float2*)&sAT[m * TP + mn0];
                float2 p  = *(const float2*)&sH[m * HP + dbase + mdl];
                mv[0][0] += a2.x * p.x;  mv[0][1] += a2.x * p.y;
                mv[1][0] += a2.y * p.x;  mv[1][1] += a2.y * p.y;
            }
#pragma unroll
            for (int i = 0; i < 2; i++) {
                int off = (mn0 + i) * HP + 64 + dbase + mdl;
                *(float2*)&sH[off] = make_float2(mv[i][0], mv[i][1]);
                st_peer_f2(u_sH + (unsigned)off * 4u, peer, mv[i][0], mv[i][1]);
            }
        }
        CLUSTER_ARRIVE();

#pragma unroll 2
        for (int kt = 0; kt < 8; kt++) {
            int kg = kt * 8;
            float a0f = sH[r0 * HP + kg + t4];
            float a1f = sH[(r0 + 8) * HP + kg + t4];
            float a2f = sH[r0 * HP + kg + t4 + 4];
            float a3f = sH[(r0 + 8) * HP + kg + t4 + 4];
            unsigned ah[4] = {f2tf(a0f), f2tf(a1f), f2tf(a2f), f2tf(a3f)};
            unsigned al[4] = {f2tf(a0f - __uint_as_float(ah[0])),
                              f2tf(a1f - __uint_as_float(ah[1])),
                              f2tf(a2f - __uint_as_float(ah[2])),
                              f2tf(a3f - __uint_as_float(ah[3]))};
#pragma unroll
            for (int nt = 0; nt < 3; nt++) {
                unsigned bh0 = sWh[(kg + t4) * WP + epb[nt] + g];
                unsigned bh1 = sWh[(kg + t4 + 4) * WP + epb[nt] + g];
                unsigned bl0 = __ldg(&g_Wl[(kg + t4) * 192 + egl[nt] + g]);
                unsigned bl1 = __ldg(&g_Wl[(kg + t4 + 4) * 192 + egl[nt] + g]);
                mma_tf32(c[nt], ah, bh0, bh1);
                mma_tf32(c[nt], al, bh0, bh1);
                mma_tf32(c[nt], ah, bl0, bl1);
            }
        }

        CLUSTER_WAIT();
        __syncthreads();

        {
            float mv[2][2] = {{0.f, 0.f}, {0.f, 0.f}};
#pragma unroll 4
            for (int m = 0; m < 64; m++) {
                float2 a2 = *(const float2*)&sAT[m * TP + mn0];
                float2 p  = *(const float2*)&sH[m * HP + 64 + dbase + mdl];
                mv[0][0] += a2.x * p.x;  mv[0][1] += a2.x * p.y;
                mv[1][0] += a2.y * p.x;  mv[1][1] += a2.y * p.y;
            }
#pragma unroll
            for (int i = 0; i < 2; i++) {
                int off = (mn0 + i) * HP + 128 + dbase + mdl;
                *(float2*)&sH[off] = make_float2(mv[i][0], mv[i][1]);
                st_peer_f2(u_sH + (unsigned)off * 4u, peer, mv[i][0], mv[i][1]);
            }
        }
        CLUSTER_ARRIVE();

#pragma unroll 2
        for (int kt = 0; kt < 8; kt++) {
            int kg = 64 + kt * 8;
            float a0f = sH[r0 * HP + kg + t4];
            float a1f = sH[(r0 + 8) * HP + kg + t4];
            float a2f = sH[r0 * HP + kg + t4 + 4];
            float a3f = sH[(r0 + 8) * HP + kg + t4 + 4];
            unsigned ah[4] = {f2tf(a0f), f2tf(a1f), f2tf(a2f), f2tf(a3f)};
            unsigned al[4] = {f2tf(a0f - __uint_as_float(ah[0])),
                              f2tf(a1f - __uint_as_float(ah[1])),
                              f2tf(a2f - __uint_as_float(ah[2])),
                              f2tf(a3f - __uint_as_float(ah[3]))};
#pragma unroll
            for (int nt = 0; nt < 3; nt++) {
                unsigned bh0 = sWh[(kg + t4) * WP + epb[nt] + g];
                unsigned bh1 = sWh[(kg + t4 + 4) * WP + epb[nt] + g];
                unsigned bl0 = __ldg(&g_Wl[(kg + t4) * 192 + egl[nt] + g]);
                unsigned bl1 = __ldg(&g_Wl[(kg + t4 + 4) * 192 + egl[nt] + g]);
                mma_tf32(c[nt], ah, bh0, bh1);
                mma_tf32(c[nt], al, bh0, bh1);
                mma_tf32(c[nt], ah, bl0, bl1);
            }
        }

        CLUSTER_WAIT();
        __syncthreads();

#pragma unroll 2
        for (int kt = 0; kt < 8; kt++) {
            int kg = 128 + kt * 8;
            float a0f = sH[r0 * HP + kg + t4];
            float a1f = sH[(r0 + 8) * HP + kg + t4];
            float a2f = sH[r0 * HP + kg + t4 + 4];
            float a3f = sH[(r0 + 8) * HP + kg + t4 + 4];
            unsigned ah[4] = {f2tf(a0f), f2tf(a1f), f2tf(a2f), f2tf(a3f)};
            unsigned al[4] = {f2tf(a0f - __uint_as_float(ah[0])),
                              f2tf(a1f - __uint_as_float(ah[1])),
                              f2tf(a2f - __uint_as_float(ah[2])),
                              f2tf(a3f - __uint_as_float(ah[3]))};
#pragma unroll
            for (int nt = 0; nt < 3; nt++) {
                unsigned bh0 = sWh[(kg + t4) * WP + epb[nt] + g];
                unsigned bh1 = sWh[(kg + t4 + 4) * WP + epb[nt] + g];
                unsigned bl0 = __ldg(&g_Wl[(kg + t4) * 192 + egl[nt] + g]);
                unsigned bl1 = __ldg(&g_Wl[(kg + t4 + 4) * 192 + egl[nt] + g]);
                mma_tf32(c[nt], ah, bh0, bh1);
                mma_tf32(c[nt], al, bh0, bh1);
                mma_tf32(c[nt], ah, bl0, bl1);
            }
        }

#pragma unroll
        for (int nt = 0; nt < 3; nt++) {
            int col = epb[nt] + 2 * t4;
            *(float2*)&sG[r0 * GP + col] = make_float2(c[nt][0], c[nt][1]);
            *(float2*)&sG[(r0 + 8) * GP + col] = make_float2(c[nt][2], c[nt][3]);
        }
        __syncthreads();

#pragma unroll
        for (int i = 0; i < 2; i++) {
            int row = mn0 + i;
            float hv[2];
#pragma unroll
            for (int j = 0; j < 2; j++) {
                float fv = sG[row * GP + mdl + j];
                float gv = sG[row * GP + 32 + mdl + j];
                float cv = sG[row * GP + 64 + mdl + j];
                float f = sig_fast(fv);
                float tg = tanh_fast(gv);
                float tc = tanh_fast(cv);
                hv[j] = f * (tg - tc) + tc;
            }
            int off = row * HP + dbase + mdl;
            *(float2*)&sH[off] = make_float2(hv[0], hv[1]);
            st_peer_f2(u_sH + (unsigned)off * 4u, peer, hv[0], hv[1]);
        }
        CLUSTER_ARRIVE();
    }

    CLUSTER_WAIT();

    if (rank == 0) {
        {
            int d = tid >> 3, q = tid & 7;
            float s = 0.f;
#pragma unroll
            for (int nn = 0; nn < 8; nn++) s += sH[(q * 8 + nn) * HP + d];
            s += __shfl_xor_sync(0xFFFFFFFFu, s, 1);
            s += __shfl_xor_sync(0xFFFFFFFFu, s, 2);
            s += __shfl_xor_sync(0xFFFFFFFFu, s, 4);
            if (q == 0)
                g_pool[((size_t)(b * NT + NT - 1)) * NH + d] = s * (1.0f / 64.0f);
        }
        float* fh = out + (size_t)NB * NT * 6 + (size_t)b * (NN * NH);
        for (int i = tid; i < 4096; i += 512)
            fh[i] = sH[(i >> 6) * HP + (i & 63)];
    }
}

// ---------------------------------------------------------------------------
// Phase 3: decoder MLP per (b,t). grid 8192, block 128.
// ---------------------------------------------------------------------------
__global__ void __launch_bounds__(128, 8) phase3_kernel(
    const float* __restrict__ dW1, const float* __restrict__ db1,
    const float* __restrict__ dW2, const float* __restrict__ db2,
    const float* __restrict__ dW3, const float* __restrict__ db3,
    const float* __restrict__ osc, const float* __restrict__ obi,
    float* __restrict__ out)
{
    __shared__ float sp[64];
    __shared__ float z1[128];
    __shared__ float z2[64];
    const int bt = blockIdx.x;
    const int tid = threadIdx.x;

    if (tid < 64) sp[tid] = g_pool[(size_t)bt * NH + tid];
    __syncthreads();
    {
        float a = db1[tid];
#pragma unroll 4
        for (int d = 0; d < 64; d++) a += sp[d] * dW1[d * 128 + tid];
        z1[tid] = fmaxf(a, 0.f);
    }
    __syncthreads();
    if (tid < 64) {
        float a = db2[tid];
#pragma unroll 4
        for (int i = 0; i < 128; i++) a += z1[i] * dW2[i * 64 + tid];
        z2[tid] = fmaxf(a, 0.f);
    }
    __syncthreads();
    if (tid < 6) {
        float a = db3[tid];
#pragma unroll 4
        for (int j = 0; j < 64; j++) a += z2[j] * dW3[j * 6 + tid];
        out[(size_t)bt * 6 + tid] = a * osc[tid] + obi[tid];
    }
}

extern "C" void kernel_launch(void* const* d_in, const int* in_sizes, int n_in,
                              void* d_out, int out_size) {
    const float* frames = (const float*)d_in[0];
    const float* adj    = (const float*)d_in[1];
    const float* h0     = (const float*)d_in[2];
    const float* encW   = (const float*)d_in[3];
    const float* encB   = (const float*)d_in[4];
    const float* Wfh    = (const float*)d_in[5];
    const float* Wfu    = (const float*)d_in[6];
    const float* bf     = (const float*)d_in[7];
    const float* Wgh    = (const float*)d_in[8];
    const float* Wgu    = (const float*)d_in[9];
    const float* bg     = (const float*)d_in[10];
    const float* Wch    = (const float*)d_in[11];
    const float* Wcu    = (const float*)d_in[12];
    const float* bc     = (const float*)d_in[13];
    const float* dW1    = (const float*)d_in[14];
    const float* db1    = (const float*)d_in[15];
    const float* dW2    = (const float*)d_in[16];
    const float* db2    = (const float*)d_in[17];
    const float* dW3    = (const float*)d_in[18];
    const float* db3    = (const float*)d_in[19];
    const float* osc    = (const float*)d_in[20];
    const float* obi    = (const float*)d_in[21];
    float* out = (float*)d_out;

    const int smem1 = 17408 * 4;   // 69632 B -> 2 CTAs/SM
    const int smem2 = 174080;
    cudaFuncSetAttribute(phase1_kernel, cudaFuncAttributeMaxDynamicSharedMemorySize, smem1);
    cudaFuncSetAttribute(phase2_kernel, cudaFuncAttributeMaxDynamicSharedMemorySize, smem2);

    prep2_kernel<<<144, 256>>>(Wfh, Wgh, Wch);
    phase1_kernel<<<NB * NT, 256, smem1>>>(frames, adj, encW, encB,
                                           Wfu, Wgu, Wcu, bf, bg, bc);
    phase2_kernel<<<NB * 2, 512, smem2>>>(adj, h0, Wfh, Wgh, Wch, out);
    phase3_kernel<<<NB * NT, 128>>>(dW1, db1, dW2, db2, dW3, db3, osc, obi, out);
}

// round 16
// speedup vs baseline: 1.2736x; 1.0099x over previous
#include <cuda_runtime.h>
#include <math.h>

#define NB 64
#define NT 128
#define NN 64
#define NC 128
#define NH 64
#define NE 192
#define TP 68
#define WP 104   // phase2 sWh pitch (u32)
#define GP 104   // phase2 sG pitch
#define HP 196   // phase2 Hcat pitch
#define PB 68    // phase1 buffer pitch

// U[b,t,n,e] fp32 (biases included). 384 MiB.
static __device__ float g_U[(size_t)NB * NT * NN * NE];
// Pooled hidden means per (b,t). 2 MiB.
static __device__ float g_pool[(size_t)NB * NT * NH];
// tf32 lo-part of hidden-path weights, [k=192][e=192]. 147 KB (L2-resident).
static __device__ unsigned g_Wl[192 * 192];

__device__ __forceinline__ unsigned smem_u32(const void* p) {
    unsigned r;
    asm("{ .reg .u64 t; cvta.to.shared.u64 t, %1; cvt.u32.u64 %0, t; }" : "=r"(r) : "l"(p));
    return r;
}
__device__ __forceinline__ unsigned cluster_rank() {
    unsigned r; asm("mov.u32 %0, %%cluster_ctarank;" : "=r"(r)); return r;
}
__device__ __forceinline__ void st_peer_f2(unsigned laddr, unsigned peer, float a, float b) {
    unsigned raddr;
    asm volatile("mapa.shared::cluster.u32 %0, %1, %2;" : "=r"(raddr) : "r"(laddr), "r"(peer));
    asm volatile("st.shared::cluster.v2.f32 [%0], {%1, %2};" :: "r"(raddr), "f"(a), "f"(b) : "memory");
}
#define CLUSTER_ARRIVE() asm volatile("barrier.cluster.arrive.aligned;" ::: "memory")
#define CLUSTER_WAIT()   asm volatile("barrier.cluster.wait.aligned;" ::: "memory")
#define CLUSTER_SYNC() do { CLUSTER_ARRIVE(); CLUSTER_WAIT(); } while (0)

__device__ __forceinline__ float rcp_ap(float x) {
    float y; asm("rcp.approx.f32 %0, %1;" : "=f"(y) : "f"(x)); return y;
}
__device__ __forceinline__ float tanh_fast(float x) {
    return 1.0f - 2.0f * rcp_ap(1.0f + __expf(2.0f * x));
}
__device__ __forceinline__ float sig_fast(float x) {
    return rcp_ap(1.0f + __expf(-x));
}
__device__ __forceinline__ unsigned f2tf(float x) {
    unsigned u; asm("cvt.rna.tf32.f32 %0, %1;" : "=r"(u) : "f"(x)); return u;
}
__device__ __forceinline__ void mma_tf32(float c[4], const unsigned a[4],
                                         unsigned b0, unsigned b1) {
    asm volatile(
        "mma.sync.aligned.m16n8k8.row.col.f32.tf32.tf32.f32 "
        "{%0,%1,%2,%3}, {%4,%5,%6,%7}, {%8,%9}, {%0,%1,%2,%3};"
        : "+f"(c[0]), "+f"(c[1]), "+f"(c[2]), "+f"(c[3])
        : "r"(a[0]), "r"(a[1]), "r"(a[2]), "r"(a[3]), "r"(b0), "r"(b1));
}

// ---------------------------------------------------------------------------
// prep2: tf32 lo-part of hidden weights, layout [k][e].
// ---------------------------------------------------------------------------
__global__ void prep2_kernel(const float* __restrict__ Wfh, const float* __restrict__ Wgh,
                             const float* __restrict__ Wch) {
    int i = blockIdx.x * 256 + threadIdx.x;
    if (i >= 36864) return;
    int k = i / 192, e = i % 192;
    int hop = k >> 6, dm = k & 63;
    int gate = e >> 6, dc = e & 63;
    const float* W = (gate == 0) ? Wfh : ((gate == 1) ? Wgh : Wch);
    float w = W[hop * 4096 + dm * 64 + dc];
    unsigned hi = f2tf(w);
    g_Wl[i] = f2tf(w - __uint_as_float(hi));
}

// ---------------------------------------------------------------------------
// Phase 1 (R15, passing): ALL tensor. grid 8192, block 256, smem 69632 B.
// ---------------------------------------------------------------------------
__device__ __forceinline__ void mm_mma(float* __restrict__ dst,
                                       const float* __restrict__ sAN,
                                       const float* __restrict__ src,
                                       int g, int t4, int col0)
{
    float cm[4][4];
#pragma unroll
    for (int mt = 0; mt < 4; mt++)
#pragma unroll
        for (int q = 0; q < 4; q++) cm[mt][q] = 0.f;

#pragma unroll 1
    for (int kc = 0; kc < 8; kc++) {
        int k0 = kc * 8;
        float x0 = src[(k0 + t4) * PB + col0 + g];
        float x1 = src[(k0 + t4 + 4) * PB + col0 + g];
        unsigned bh0 = f2tf(x0), bh1 = f2tf(x1);
        unsigned bl0 = f2tf(x0 - __uint_as_float(bh0));
        unsigned bl1 = f2tf(x1 - __uint_as_float(bh1));
#pragma unroll
        for (int mt = 0; mt < 4; mt++) {
            int r0 = mt * 16 + g;
            float a0f = sAN[r0 * PB + k0 + t4];
            float a1f = sAN[(r0 + 8) * PB + k0 + t4];
            float a2f = sAN[r0 * PB + k0 + t4 + 4];
            float a3f = sAN[(r0 + 8) * PB + k0 + t4 + 4];
            unsigned ah[4] = {f2tf(a0f), f2tf(a1f), f2tf(a2f), f2tf(a3f)};
            unsigned al[4] = {f2tf(a0f - __uint_as_float(ah[0])),
                              f2tf(a1f - __uint_as_float(ah[1])),
                              f2tf(a2f - __uint_as_float(ah[2])),
                              f2tf(a3f - __uint_as_float(ah[3]))};
            mma_tf32(cm[mt], ah, bh0, bh1);
            mma_tf32(cm[mt], al, bh0, bh1);
            mma_tf32(cm[mt], ah, bl0, bl1);
        }
    }
#pragma unroll
    for (int mt = 0; mt < 4; mt++) {
        int r0 = mt * 16 + g;
        *(float2*)&dst[r0 * PB + col0 + 2 * t4] = make_float2(cm[mt][0], cm[mt][1]);
        *(float2*)&dst[(r0 + 8) * PB + col0 + 2 * t4] = make_float2(cm[mt][2], cm[mt][3]);
    }
}

__global__ void __launch_bounds__(256, 2) phase1_kernel(
    const float* __restrict__ frames, const float* __restrict__ adj,
    const float* __restrict__ encW, const float* __restrict__ encB,
    const float* __restrict__ Wfu, const float* __restrict__ Wgu, const float* __restrict__ Wcu,
    const float* __restrict__ bf, const float* __restrict__ bg, const float* __restrict__ bc)
{
    extern __shared__ float sm[];
    float* sAN = sm;               // 4352
    float* sX  = sm + 4352;
    float* sY1 = sm + 8704;
    float* sY2 = sm + 13056;

    const int tid = threadIdx.x;
    const int bt = blockIdx.x;
    const float* fr = frames + (size_t)bt * (NC * NN);
    const float* Ap = adj + (size_t)bt * (NN * NN);

    for (int i = tid; i < NN * NN; i += 256) {
        int n = i >> 6, m = i & 63;
        sAN[n * PB + m] = Ap[i];
    }

    const int w = tid >> 5;
    const int lane = tid & 31;
    const int g = lane >> 2;
    const int t4 = lane & 3;
    const int col0 = w * 8;

    // encode
    {
        float ce[4][4];
        {
            float b0v = __ldg(&encB[col0 + 2 * t4]);
            float b1v = __ldg(&encB[col0 + 2 * t4 + 1]);
#pragma unroll
            for (int mt = 0; mt < 4; mt++) {
                ce[mt][0] = b0v; ce[mt][1] = b1v;
                ce[mt][2] = b0v; ce[mt][3] = b1v;
            }
        }
#pragma unroll 1
        for (int kc = 0; kc < 16; kc++) {
            int k0 = kc * 8;
            float w0 = __ldg(&encW[(k0 + t4) * 64 + col0 + g]);
            float w1 = __ldg(&encW[(k0 + t4 + 4) * 64 + col0 + g]);
            unsigned bh0 = f2tf(w0), bh1 = f2tf(w1);
            unsigned bl0 = f2tf(w0 - __uint_as_float(bh0));
            unsigned bl1 = f2tf(w1 - __uint_as_float(bh1));
#pragma unroll
            for (int mt = 0; mt < 4; mt++) {
                int r0 = mt * 16 + g;
                float a0f = __ldg(&fr[(k0 + t4) * 64 + r0]);
                float a1f = __ldg(&fr[(k0 + t4) * 64 + r0 + 8]);
                float a2f = __ldg(&fr[(k0 + t4 + 4) * 64 + r0]);
                float a3f = __ldg(&fr[(k0 + t4 + 4) * 64 + r0 + 8]);
                unsigned ah[4] = {f2tf(a0f), f2tf(a1f), f2tf(a2f), f2tf(a3f)};
                unsigned al[4] = {f2tf(a0f - __uint_as_float(ah[0])),
                                  f2tf(a1f - __uint_as_float(ah[1])),
                                  f2tf(a2f - __uint_as_float(ah[2])),
                                  f2tf(a3f - __uint_as_float(ah[3]))};
                mma_tf32(ce[mt], ah, bh0, bh1);
                mma_tf32(ce[mt], al, bh0, bh1);
                mma_tf32(ce[mt], ah, bl0, bl1);
            }
        }
#pragma unroll
        for (int mt = 0; mt < 4; mt++) {
            int r0 = mt * 16 + g;
            *(float2*)&sX[r0 * PB + col0 + 2 * t4] = make_float2(ce[mt][0], ce[mt][1]);
            *(float2*)&sX[(r0 + 8) * PB + col0 + 2 * t4] = make_float2(ce[mt][2], ce[mt][3]);
        }
    }
    __syncthreads();

    mm_mma(sY1, sAN, sX, g, t4, col0);
    __syncthreads();
    mm_mma(sY2, sAN, sY1, g, t4, col0);
    __syncthreads();

    // gate GEMM
    const int e0 = w * 24;
    const float* Wp[3];
    const float* Bp[3];
    int dcn[3];
#pragma unroll
    for (int nt = 0; nt < 3; nt++) {
        int e = e0 + nt * 8;
        int gate = e >> 6;
        dcn[nt] = e & 63;
        Wp[nt] = (gate == 0) ? Wfu : ((gate == 1) ? Wgu : Wcu);
        Bp[nt] = (gate == 0) ? bf  : ((gate == 1) ? bg  : bc);
    }

    float cacc[4][3][4];
#pragma unroll
    for (int nt = 0; nt < 3; nt++) {
        float b0v = __ldg(Bp[nt] + dcn[nt] + 2 * t4);
        float b1v = __ldg(Bp[nt] + dcn[nt] + 2 * t4 + 1);
#pragma unroll
        for (int mt = 0; mt < 4; mt++) {
            cacc[mt][nt][0] = b0v; cacc[mt][nt][1] = b1v;
            cacc[mt][nt][2] = b0v; cacc[mt][nt][3] = b1v;
        }
    }

    const float* bufs[3] = {sX, sY1, sY2};
#pragma unroll 1
    for (int kt = 0; kt < 24; kt++) {
        const int hop = kt >> 3;
        const int dk0 = (kt & 7) * 8;
        const float* Bf = bufs[hop];

        float afv[4][4];
        unsigned ah[4][4];
#pragma unroll
        for (int mt = 0; mt < 4; mt++) {
            int r0 = (mt * 16 + g) * PB;
            int r1 = r0 + 8 * PB;
            afv[mt][0] = Bf[r0 + dk0 + t4];
            afv[mt][1] = Bf[r1 + dk0 + t4];
            afv[mt][2] = Bf[r0 + dk0 + t4 + 4];
            afv[mt][3] = Bf[r1 + dk0 + t4 + 4];
#pragma unroll
            for (int q = 0; q < 4; q++) ah[mt][q] = f2tf(afv[mt][q]);
        }

        unsigned bh[3][2];
#pragma unroll
        for (int nt = 0; nt < 3; nt++) {
            const float* W = Wp[nt];
            int base = hop * 4096 + (dk0 + t4) * 64 + dcn[nt] + g;
            float w0 = __ldg(W + base);
            float w1 = __ldg(W + base + 256);
            bh[nt][0] = f2tf(w0);
            bh[nt][1] = f2tf(w1);
            unsigned bl0 = f2tf(w0 - __uint_as_float(bh[nt][0]));
            unsigned bl1 = f2tf(w1 - __uint_as_float(bh[nt][1]));
#pragma unroll
            for (int mt = 0; mt < 4; mt++) {
                mma_tf32(cacc[mt][nt], ah[mt], bh[nt][0], bh[nt][1]);
                mma_tf32(cacc[mt][nt], ah[mt], bl0, bl1);
            }
        }

        unsigned al[4][4];
#pragma unroll
        for (int mt = 0; mt < 4; mt++)
#pragma unroll
            for (int q = 0; q < 4; q++)
                al[mt][q] = f2tf(afv[mt][q] - __uint_as_float(ah[mt][q]));
#pragma unroll
        for (int nt = 0; nt < 3; nt++)
#pragma unroll
            for (int mt = 0; mt < 4; mt++)
                mma_tf32(cacc[mt][nt], al[mt], bh[nt][0], bh[nt][1]);
    }

    float* Ub = g_U + (size_t)bt * (NN * NE);
#pragma unroll
    for (int mt = 0; mt < 4; mt++) {
        int row = mt * 16 + g;
#pragma unroll
        for (int nt = 0; nt < 3; nt++) {
            int col = e0 + nt * 8 + 2 * t4;
            *(float2*)&Ub[row * NE + col] = make_float2(cacc[mt][nt][0], cacc[mt][nt][1]);
            *(float2*)&Ub[(row + 8) * NE + col] = make_float2(cacc[mt][nt][2], cacc[mt][nt][3]);
        }
    }
}

// ---------------------------------------------------------------------------
// Phase 2: e/d-split cluster recurrence, ONE exchange per step.
// Both CTAs compute full h1/h2 locally via 3xTF32 mma (no mid-step exchange).
// grid 128 (64 clusters of 2), block 512. smem = 174080 B.
// ---------------------------------------------------------------------------
// Full 64x64 mm for 16 warps: dst[n][col] = A @ src. A = sAN [n][m] pitch TP,
// src/dst pitch HP (pass pointers offset to the hop column base).
__device__ __forceinline__ void mm_mma2(float* __restrict__ dst,
                                        const float* __restrict__ sAN,
                                        const float* __restrict__ src,
                                        int g, int t4, int colm, int mt2)
{
    float cm[2][4];
#pragma unroll
    for (int i = 0; i < 2; i++)
#pragma unroll
        for (int q = 0; q < 4; q++) cm[i][q] = 0.f;

#pragma unroll 1
    for (int kc = 0; kc < 8; kc++) {
        int k0 = kc * 8;
        float x0 = src[(k0 + t4) * HP + colm + g];
        float x1 = src[(k0 + t4 + 4) * HP + colm + g];
        unsigned bh0 = f2tf(x0), bh1 = f2tf(x1);
        unsigned bl0 = f2tf(x0 - __uint_as_float(bh0));
        unsigned bl1 = f2tf(x1 - __uint_as_float(bh1));
#pragma unroll
        for (int i = 0; i < 2; i++) {
            int r0 = (mt2 + i) * 16 + g;
            float a0f = sAN[r0 * TP + k0 + t4];
            float a1f = sAN[(r0 + 8) * TP + k0 + t4];
            float a2f = sAN[r0 * TP + k0 + t4 + 4];
            float a3f = sAN[(r0 + 8) * TP + k0 + t4 + 4];
            unsigned ah[4] = {f2tf(a0f), f2tf(a1f), f2tf(a2f), f2tf(a3f)};
            unsigned al[4] = {f2tf(a0f - __uint_as_float(ah[0])),
                              f2tf(a1f - __uint_as_float(ah[1])),
                              f2tf(a2f - __uint_as_float(ah[2])),
                              f2tf(a3f - __uint_as_float(ah[3]))};
            mma_tf32(cm[i], ah, bh0, bh1);
            mma_tf32(cm[i], al, bh0, bh1);
            mma_tf32(cm[i], ah, bl0, bl1);
        }
    }
#pragma unroll
    for (int i = 0; i < 2; i++) {
        int r0 = (mt2 + i) * 16 + g;
        *(float2*)&dst[r0 * HP + colm + 2 * t4] = make_float2(cm[i][0], cm[i][1]);
        *(float2*)&dst[(r0 + 8) * HP + colm + 2 * t4] = make_float2(cm[i][2], cm[i][3]);
    }
}

__global__ void __launch_bounds__(512, 1) __cluster_dims__(2, 1, 1) phase2_kernel(
    const float* __restrict__ adj, const float* __restrict__ h0,
    const float* __restrict__ Wfh, const float* __restrict__ Wgh, const float* __restrict__ Wch,
    float* __restrict__ out)
{
    extern __shared__ char smc[];
    unsigned* sWh = (unsigned*)smc;              // 192 x WP u32: 79872
    float* sH  = (float*)(smc + 79872);          // 64 x HP: 50176
    float* sAN = (float*)(smc + 130048);         // 64 x TP natural A: 17408
    float* sG  = (float*)(smc + 147456);         // 64 x GP: 26624

    const int tid = threadIdx.x;
    const int b = blockIdx.x >> 1;
    const unsigned rank = cluster_rank();
    const unsigned peer = rank ^ 1u;
    const int dbase = (int)rank * 32;

    for (int i = tid; i < 192 * 96; i += 512) {
        int k = i / 96, ep = i % 96;
        int gate = ep >> 5, dloc = ep & 31;
        int hop = k >> 6, dm = k & 63;
        const float* W = (gate == 0) ? Wfh : ((gate == 1) ? Wgh : Wch);
        sWh[k * WP + ep] = f2tf(W[hop * 4096 + dm * 64 + dbase + dloc]);
    }
    for (int i = tid; i < 4096; i += 512) {
        int n = i >> 6, d = i & 63;
        sH[n * HP + d] = h0[b * 4096 + i];
    }
    __syncthreads();
    CLUSTER_SYNC();
    CLUSTER_ARRIVE();   // pre-arm: loop starts with WAIT

    const unsigned u_sH = smem_u32(sH);

    // h_new mapping: 2n x 2d-local per thread
    const int mn0 = (tid >> 4) * 2;
    const int mdl = (tid & 15) * 2;

    // mma mappings
    const int w = tid >> 5, lane = tid & 31;
    const int g = lane >> 2, t4 = lane & 3;
    // gates (16 warps: mt = w&3, ng = w>>2)
    const int mt = w & 3, ng = w >> 2;
    const int r0 = mt * 16 + g;
    // mm (16 warps: colm = (w&7)*8, mt2 = (w>>3)*2)
    const int colm = (w & 7) * 8;
    const int mt2 = (w >> 3) * 2;

    int epb[3], egl[3];
#pragma unroll
    for (int nt = 0; nt < 3; nt++) {
        epb[nt] = (ng * 3 + nt) * 8;
        int gate = epb[nt] >> 5;
        egl[nt] = gate * 64 + dbase + (epb[nt] & 31);
    }

    float2 pu[6];
    {
        const float* Ub = g_U + ((size_t)(b * NT)) * (NN * NE);
#pragma unroll
        for (int nt = 0; nt < 3; nt++) {
            pu[nt * 2]     = *(const float2*)&Ub[r0 * NE + egl[nt] + 2 * t4];
            pu[nt * 2 + 1] = *(const float2*)&Ub[(r0 + 8) * NE + egl[nt] + 2 * t4];
        }
    }

    for (int t = 0; t < NT; t++) {
        CLUSTER_WAIT();    // full h(t) (peer own-col pushes of step t-1)
        __syncthreads();   // local h_new writes visible; prev-step sAN reads done

        // accumulators from prefetched U; prefetch next
        float c[3][4];
#pragma unroll
        for (int nt = 0; nt < 3; nt++) {
            c[nt][0] = pu[nt * 2].x;     c[nt][1] = pu[nt * 2].y;
            c[nt][2] = pu[nt * 2 + 1].x; c[nt][3] = pu[nt * 2 + 1].y;
        }
        {
            int btn = b * NT + t + 1;
            if (btn > NB * NT - 1) btn = NB * NT - 1;
            const float* Ub = g_U + (size_t)btn * (NN * NE);
#pragma unroll
            for (int nt = 0; nt < 3; nt++) {
                pu[nt * 2]     = *(const float2*)&Ub[r0 * NE + egl[nt] + 2 * t4];
                pu[nt * 2 + 1] = *(const float2*)&Ub[(r0 + 8) * NE + egl[nt] + 2 * t4];
            }
        }
        // pool of h(t) -> g_pool[t-1] (reads hop0 only)
        if (rank == 0 && t > 0) {
            int d = tid >> 3, q = tid & 7;
            float s = 0.f;
#pragma unroll
            for (int nn = 0; nn < 8; nn++) s += sH[(q * 8 + nn) * HP + d];
            s += __shfl_xor_sync(0xFFFFFFFFu, s, 1);
            s += __shfl_xor_sync(0xFFFFFFFFu, s, 2);
            s += __shfl_xor_sync(0xFFFFFFFFu, s, 4);
            if (q == 0)
                g_pool[((size_t)(b * NT + t - 1)) * NH + d] = s * (1.0f / 64.0f);
        }
        // stage adjacency natural [n][m] (direct float4 copy)
        {
            const float4* Ap4 = (const float4*)(adj + ((size_t)(b * NT + t)) * 4096);
            for (int i = tid; i < 1024; i += 512) {
                int n = i >> 4, q = i & 15;
                *(float4*)&sAN[n * TP + q * 4] = __ldg(&Ap4[i]);
            }
        }
        __syncthreads();   // sAN ready

        // mm1: full h1 = A @ h (both CTAs, local)
        mm_mma2(sH + 64, sAN, sH, g, t4, colm, mt2);
        __syncthreads();
        // mm2: full h2 = A @ h1
        mm_mma2(sH + 128, sAN, sH + 64, g, t4, colm, mt2);
        __syncthreads();

        // gates: 3 hops back-to-back (all local)
#pragma unroll 1
        for (int hop = 0; hop < 3; hop++) {
            int kb = hop * 64;
#pragma unroll 2
            for (int kt = 0; kt < 8; kt++) {
                int kg = kb + kt * 8;
                float a0f = sH[r0 * HP + kg + t4];
                float a1f = sH[(r0 + 8) * HP + kg + t4];
                float a2f = sH[r0 * HP + kg + t4 + 4];
                float a3f = sH[(r0 + 8) * HP + kg + t4 + 4];
                unsigned ah[4] = {f2tf(a0f), f2tf(a1f), f2tf(a2f), f2tf(a3f)};
                unsigned al[4] = {f2tf(a0f - __uint_as_float(ah[0])),
                                  f2tf(a1f - __uint_as_float(ah[1])),
                                  f2tf(a2f - __uint_as_float(ah[2])),
                                  f2tf(a3f - __uint_as_float(ah[3]))};
#pragma unroll
                for (int nt = 0; nt < 3; nt++) {
                    unsigned bh0 = sWh[(kg + t4) * WP + epb[nt] + g];
                    unsigned bh1 = sWh[(kg + t4 + 4) * WP + epb[nt] + g];
                    unsigned bl0 = __ldg(&g_Wl[(kg + t4) * 192 + egl[nt] + g]);
                    unsigned bl1 = __ldg(&g_Wl[(kg + t4 + 4) * 192 + egl[nt] + g]);
                    mma_tf32(c[nt], ah, bh0, bh1);
                    mma_tf32(c[nt], al, bh0, bh1);
                    mma_tf32(c[nt], ah, bl0, bl1);
                }
            }
        }

        // store G tiles
#pragma unroll
        for (int nt = 0; nt < 3; nt++) {
            int col = epb[nt] + 2 * t4;
            *(float2*)&sG[r0 * GP + col] = make_float2(c[nt][0], c[nt][1]);
            *(float2*)&sG[(r0 + 8) * GP + col] = make_float2(c[nt][2], c[nt][3]);
        }
        __syncthreads();   // sG complete; all gate reads of sH done

        // nonlinearity -> h_new own d-cols; write local + push peer
#pragma unroll
        for (int i = 0; i < 2; i++) {
            int row = mn0 + i;
            float hv[2];
#pragma unroll
            for (int j = 0; j < 2; j++) {
                float fv = sG[row * GP + mdl + j];
                float gv = sG[row * GP + 32 + mdl + j];
                float cv = sG[row * GP + 64 + mdl + j];
                float f = sig_fast(fv);
                float tg = tanh_fast(gv);
                float tc = tanh_fast(cv);
                hv[j] = f * (tg - tc) + tc;
            }
            int off = row * HP + dbase + mdl;
            *(float2*)&sH[off] = make_float2(hv[0], hv[1]);
            st_peer_f2(u_sH + (unsigned)off * 4u, peer, hv[0], hv[1]);
        }
        CLUSTER_ARRIVE();
    }

    CLUSTER_WAIT();   // final h full

    if (rank == 0) {
        {
            int d = tid >> 3, q = tid & 7;
            float s = 0.f;
#pragma unroll
            for (int nn = 0; nn < 8; nn++) s += sH[(q * 8 + nn) * HP + d];
            s += __shfl_xor_sync(0xFFFFFFFFu, s, 1);
            s += __shfl_xor_sync(0xFFFFFFFFu, s, 2);
            s += __shfl_xor_sync(0xFFFFFFFFu, s, 4);
            if (q == 0)
                g_pool[((size_t)(b * NT + NT - 1)) * NH + d] = s * (1.0f / 64.0f);
        }
        float* fh = out + (size_t)NB * NT * 6 + (size_t)b * (NN * NH);
        for (int i = tid; i < 4096; i += 512)
            fh[i] = sH[(i >> 6) * HP + (i & 63)];
    }
}

// ---------------------------------------------------------------------------
// Phase 3: decoder MLP per (b,t). grid 8192, block 128.
// ---------------------------------------------------------------------------
__global__ void __launch_bounds__(128, 8) phase3_kernel(
    const float* __restrict__ dW1, const float* __restrict__ db1,
    const float* __restrict__ dW2, const float* __restrict__ db2,
    const float* __restrict__ dW3, const float* __restrict__ db3,
    const float* __restrict__ osc, const float* __restrict__ obi,
    float* __restrict__ out)
{
    __shared__ float sp[64];
    __shared__ float z1[128];
    __shared__ float z2[64];
    const int bt = blockIdx.x;
    const int tid = threadIdx.x;

    if (tid < 64) sp[tid] = g_pool[(size_t)bt * NH + tid];
    __syncthreads();
    {
        float a = db1[tid];
#pragma unroll 4
        for (int d = 0; d < 64; d++) a += sp[d] * dW1[d * 128 + tid];
        z1[tid] = fmaxf(a, 0.f);
    }
    __syncthreads();
    if (tid < 64) {
        float a = db2[tid];
#pragma unroll 4
        for (int i = 0; i < 128; i++) a += z1[i] * dW2[i * 64 + tid];
        z2[tid] = fmaxf(a, 0.f);
    }
    __syncthreads();
    if (tid < 6) {
        float a = db3[tid];
#pragma unroll 4
        for (int j = 0; j < 64; j++) a += z2[j] * dW3[j * 6 + tid];
        out[(size_t)bt * 6 + tid] = a * osc[tid] + obi[tid];
    }
}

extern "C" void kernel_launch(void* const* d_in, const int* in_sizes, int n_in,
                              void* d_out, int out_size) {
    const float* frames = (const float*)d_in[0];
    const float* adj    = (const float*)d_in[1];
    const float* h0     = (const float*)d_in[2];
    const float* encW   = (const float*)d_in[3];
    const float* encB   = (const float*)d_in[4];
    const float* Wfh    = (const float*)d_in[5];
    const float* Wfu    = (const float*)d_in[6];
    const float* bf     = (const float*)d_in[7];
    const float* Wgh    = (const float*)d_in[8];
    const float* Wgu    = (const float*)d_in[9];
    const float* bg     = (const float*)d_in[10];
    const float* Wch    = (const float*)d_in[11];
    const float* Wcu    = (const float*)d_in[12];
    const float* bc     = (const float*)d_in[13];
    const float* dW1    = (const float*)d_in[14];
    const float* db1    = (const float*)d_in[15];
    const float* dW2    = (const float*)d_in[16];
    const float* db2    = (const float*)d_in[17];
    const float* dW3    = (const float*)d_in[18];
    const float* db3    = (const float*)d_in[19];
    const float* osc    = (const float*)d_in[20];
    const float* obi    = (const float*)d_in[21];
    float* out = (float*)d_out;

    const int smem1 = 17408 * 4;   // 69632 B -> 2 CTAs/SM
    const int smem2 = 174080;
    cudaFuncSetAttribute(phase1_kernel, cudaFuncAttributeMaxDynamicSharedMemorySize, smem1);
    cudaFuncSetAttribute(phase2_kernel, cudaFuncAttributeMaxDynamicSharedMemorySize, smem2);

    prep2_kernel<<<144, 256>>>(Wfh, Wgh, Wch);
    phase1_kernel<<<NB * NT, 256, smem1>>>(frames, adj, encW, encB,
                                           Wfu, Wgu, Wcu, bf, bg, bc);
    phase2_kernel<<<NB * 2, 512, smem2>>>(adj, h0, Wfh, Wgh, Wch, out);
    phase3_kernel<<<NB * NT, 128>>>(dW1, db1, dW2, db2, dW3, db3, osc, obi, out);
}